// round 6
// baseline (speedup 1.0000x reference)
#include <cuda_runtime.h>
#include <cuda_bf16.h>
#include <math.h>
#include <stdint.h>

#define NN 50000
#define NE 600000
#define EPS_V 1e-5f
#define AVG_D_LOG 1.6094379124341003f

typedef unsigned long long u64;

// ---------------- scratch ----------------
__device__ float g_PQ[(size_t)NN * 256];            // [P | Q+b_pre]
__device__ __nv_bfloat16 g_hH[(size_t)NN * 128];
__device__ __nv_bfloat16 g_hL[(size_t)NN * 128];
__device__ __nv_bfloat16 g_aggH[(size_t)NN * 512];
__device__ __nv_bfloat16 g_aggL[(size_t)NN * 512];
__device__ __nv_bfloat16 g_hpH[(size_t)NN * 128];
__device__ __nv_bfloat16 g_hpL[(size_t)NN * 128];
__device__ float g_G[(size_t)NN * 384];
__device__ float g_s1[NN];
__device__ float g_s2[NN];
__device__ int   g_count[NN];
__device__ int   g_offsets[NN + 1];
__device__ int   g_cursor[NN];
__device__ int   g_sorted_src[NE];
__device__ float g_bias1[256];
__device__ __nv_bfloat16 g_B1Th[256 * 128];
__device__ __nv_bfloat16 g_B1Tl[256 * 128];
__device__ __nv_bfloat16 g_Wp0Th[128 * 128];
__device__ __nv_bfloat16 g_Wp0Tl[128 * 128];
__device__ __nv_bfloat16 g_WmixTh[128 * 128];
__device__ __nv_bfloat16 g_WmixTl[128 * 128];
__device__ __nv_bfloat16 g_WcatTh[384 * 512];
__device__ __nv_bfloat16 g_WcatTl[384 * 512];
__device__ int   g_blocksums[64];
__device__ int   g_blockoff[64];
__device__ int   g_is64;

// ---------------- helpers ----------------
__global__ void detect_kernel(const void* edst) {
    const int* v = (const int*)edst;
    g_is64 = (v[1] == 0 && v[3] == 0) ? 1 : 0;
}
__device__ __forceinline__ int edge_index(const void* p, int i) {
    if (g_is64) return (int)(((const long long*)p)[i]);
    return ((const int*)p)[i];
}
__device__ __forceinline__ void split2(float v, __nv_bfloat16* hi, __nv_bfloat16* lo) {
    __nv_bfloat16 h = __float2bfloat16(v);
    *hi = h;
    *lo = __float2bfloat16(v - __bfloat162float(h));
}

// ---------------- prep ----------------
__global__ void prep_kernel(const float* __restrict__ W_pre,
                            const float* __restrict__ b_pre,
                            const float* __restrict__ W_post,
                            const float* __restrict__ W_mix) {
    int idx = blockIdx.x * blockDim.x + threadIdx.x;
    if (idx < NN) g_count[idx] = 0;
    if (idx < 256) g_bias1[idx] = (idx < 128) ? 0.f : b_pre[idx - 128];
    if (idx < 256 * 128) {
        int n = idx >> 7, k = idx & 127;
        float v = (n < 128) ? W_pre[k * 128 + n] : W_pre[(128 + k) * 128 + (n - 128)];
        split2(v, &g_B1Th[idx], &g_B1Tl[idx]);
    }
    if (idx < 128 * 128) {
        int n = idx >> 7, k = idx & 127;
        split2(W_post[k * 128 + n], &g_Wp0Th[idx], &g_Wp0Tl[idx]);
        split2(W_mix[k * 128 + n], &g_WmixTh[idx], &g_WmixTl[idx]);
    }
    if (idx < 384 * 512) {
        int n = idx >> 9, k = idx & 511;
        int grp = n >> 7, jj = n & 127;
        split2(W_post[(size_t)(128 + grp * 512 + k) * 128 + jj], &g_WcatTh[idx], &g_WcatTl[idx]);
    }
}

__global__ void __launch_bounds__(256) split_h_kernel(const float* __restrict__ h) {
    int i = blockIdx.x * blockDim.x + threadIdx.x;
    int idx = i * 4;
    if (idx < NN * 128) {
        float4 v = *(const float4*)(h + idx);
        float vv[4] = {v.x, v.y, v.z, v.w};
        #pragma unroll
        for (int j = 0; j < 4; j++)
            split2(vv[j], &g_hH[idx + j], &g_hL[idx + j]);
    }
}

// ---------------- histogram / scan / scatter ----------------
__global__ void hist_kernel(const void* __restrict__ edst) {
    int e = blockIdx.x * blockDim.x + threadIdx.x;
    if (e < NE) atomicAdd(&g_count[edge_index(edst, e)], 1);
}

#define SCAN_BLOCKS ((NN + 1023) / 1024)

__global__ void __launch_bounds__(1024) scanA_kernel() {
    __shared__ int sdata[1024];
    int tid = threadIdx.x;
    int i = blockIdx.x * 1024 + tid;
    int v = (i < NN) ? g_count[i] : 0;
    sdata[tid] = v;
    __syncthreads();
    #pragma unroll
    for (int off = 1; off < 1024; off <<= 1) {
        int t = (tid >= off) ? sdata[tid - off] : 0;
        __syncthreads();
        sdata[tid] += t;
        __syncthreads();
    }
    if (i < NN) g_offsets[i] = sdata[tid] - v;
    if (tid == 1023) g_blocksums[blockIdx.x] = sdata[1023];
}
__global__ void scanB_kernel() {
    if (threadIdx.x == 0) {
        int run = 0;
        for (int b = 0; b < SCAN_BLOCKS; b++) { g_blockoff[b] = run; run += g_blocksums[b]; }
    }
}
__global__ void __launch_bounds__(1024) scanC_kernel() {
    int i = blockIdx.x * 1024 + threadIdx.x;
    if (i < NN) {
        int o = g_offsets[i] + g_blockoff[blockIdx.x];
        g_offsets[i] = o;
        g_cursor[i] = o;
    }
    if (i == 0) g_offsets[NN] = NE;
}

__global__ void scatter_kernel(const void* __restrict__ esrc, const void* __restrict__ edst) {
    int e = blockIdx.x * blockDim.x + threadIdx.x;
    if (e < NE) {
        int d = edge_index(edst, e);
        int s = edge_index(esrc, e);
        g_sorted_src[atomicAdd(&g_cursor[d], 1)] = s;
    }
}

// ---------------- aggregate ----------------
__global__ void __launch_bounds__(128) aggregate_kernel() {
    int n = blockIdx.x;
    int d = threadIdx.x;
    int start = g_offsets[n];
    int end = g_offsets[n + 1];
    float qd = g_PQ[(size_t)n * 256 + 128 + d];
    float s0 = 0.f, sq0 = 0.f, s1a = 0.f, sq1 = 0.f;
    float mx = -3.4e38f, mn = 3.4e38f;
    int i = start;
    for (; i + 1 < end; i += 2) {
        int sa = g_sorted_src[i];
        int sb = g_sorted_src[i + 1];
        float va = fmaxf(g_PQ[(size_t)sa * 256 + d] + qd, 0.f);
        float vb = fmaxf(g_PQ[(size_t)sb * 256 + d] + qd, 0.f);
        s0 += va; sq0 += va * va;
        s1a += vb; sq1 += vb * vb;
        mx = fmaxf(mx, fmaxf(va, vb));
        mn = fminf(mn, fminf(va, vb));
    }
    if (i < end) {
        int sa = g_sorted_src[i];
        float va = fmaxf(g_PQ[(size_t)sa * 256 + d] + qd, 0.f);
        s0 += va; sq0 += va * va;
        mx = fmaxf(mx, va); mn = fminf(mn, va);
    }
    float s = s0 + s1a, sq = sq0 + sq1;
    float degf = (float)(end - start);
    float inv = 1.f / degf;
    float mean = s * inv;
    float var = fmaxf(sq * inv - mean * mean, 0.f);
    float sd = sqrtf(var + EPS_V);
    size_t base = (size_t)n * 512;
    float vals[4] = {mean, mx, mn, sd};
    #pragma unroll
    for (int t = 0; t < 4; t++)
        split2(vals[t], &g_aggH[base + t * 128 + d], &g_aggL[base + t * 128 + d]);
    if (d == 0) {
        float ld = logf(degf + 1.f);
        g_s1[n] = ld / AVG_D_LOG;
        g_s2[n] = AVG_D_LOG / ld;
    }
}

// ---------------- unified bf16-split mma.sync GEMM (ldmatrix + cp.async pipeline) ----------------
#define MMA16816(c, a, b) \
    asm volatile("mma.sync.aligned.m16n8k16.row.col.f32.bf16.bf16.f32 " \
        "{%0,%1,%2,%3}, {%4,%5,%6,%7}, {%8,%9}, {%0,%1,%2,%3};" \
        : "+f"((c)[0]), "+f"((c)[1]), "+f"((c)[2]), "+f"((c)[3]) \
        : "r"((a)[0]), "r"((a)[1]), "r"((a)[2]), "r"((a)[3]), \
          "r"((b)[0]), "r"((b)[1]))

#define LDSM4(r, a) \
    asm volatile("ldmatrix.sync.aligned.m8n8.x4.shared.b16 {%0,%1,%2,%3}, [%4];" \
        : "=r"((r)[0]), "=r"((r)[1]), "=r"((r)[2]), "=r"((r)[3]) : "r"(a))

#define CPA16(dst, src) asm volatile("cp.async.ca.shared.global [%0], [%1], 16;" :: "r"(dst), "l"(src))
#define CPA_COMMIT()    asm volatile("cp.async.commit_group;" ::: "memory")
#define CPA_WAIT0()     asm volatile("cp.async.wait_group 0;" ::: "memory")

#define G2_S 72
#define STAGE_ELEMS (4 * 128 * G2_S)                 // bf16 elements per stage
#define STAGE_BYTES (STAGE_ELEMS * 2)
#define G2_SMEM_BYTES (2 * STAGE_BYTES)              // 147456

__global__ void __launch_bounds__(256, 1) tgemm_kernel(
    const __nv_bfloat16* __restrict__ aHp, const __nv_bfloat16* __restrict__ aLp,
    const __nv_bfloat16* __restrict__ bHp, const __nv_bfloat16* __restrict__ bLp,
    float* __restrict__ C, int M, int N, int K, int mode,
    const float* __restrict__ bias, const float* __restrict__ Gx,
    const float* __restrict__ s1p, const float* __restrict__ s2p,
    const float* __restrict__ resid,
    __nv_bfloat16* __restrict__ outH, __nv_bfloat16* __restrict__ outL)
{
    extern __shared__ __nv_bfloat16 sm[];
    uint32_t smem_base = (uint32_t)__cvta_generic_to_shared(sm);

    int tid = threadIdx.x, lane = tid & 31, wid = tid >> 5;
    int warp_m = wid >> 2;
    int warp_n = wid & 3;
    int blockRow = blockIdx.x * 128, blockCol = blockIdx.y * 128;

    float acc[4][4][4];
    #pragma unroll
    for (int i = 0; i < 4; i++)
        #pragma unroll
        for (int j = 0; j < 4; j++)
            #pragma unroll
            for (int q = 0; q < 4; q++) acc[i][j][q] = 0.f;

    // ---- global->smem loader mapping (cp.async) ----
    int ldRow = tid >> 1, ldHalf = tid & 1;
    int aRow = blockRow + ldRow; if (aRow > M - 1) aRow = M - 1;
    const __nv_bfloat16* gA_H = aHp + (size_t)aRow * K + ldHalf * 32;
    const __nv_bfloat16* gA_L = aLp + (size_t)aRow * K + ldHalf * 32;
    const __nv_bfloat16* gB_H = bHp + (size_t)(blockCol + ldRow) * K + ldHalf * 32;
    const __nv_bfloat16* gB_L = bLp + (size_t)(blockCol + ldRow) * K + ldHalf * 32;
    uint32_t sRowOff = (uint32_t)(ldRow * G2_S + ldHalf * 32) * 2;   // bytes within array

    // ---- ldmatrix per-lane address components ----
    int lane7 = lane & 7;
    int aRowSel = ((lane >> 3) & 1) * 8;
    int aKSel   = ((lane >> 4) & 1) * 8;
    int bRowSel = ((lane >> 4) & 1) * 8;
    int bKSel   = ((lane >> 3) & 1) * 8;

    int nch = K >> 6;

    // prologue: load chunk 0 into stage 0
    {
        uint32_t st0 = smem_base + sRowOff;
        #pragma unroll
        for (int j = 0; j < 4; j++) {
            CPA16(st0 + 0 * STAGE_ELEMS * 0 + j * 16 + 0 * 2 * 128 * G2_S, (const char*)(gA_H + j * 8));
        }
        // (expanded explicitly below to keep offsets clear)
        #pragma unroll
        for (int j = 0; j < 4; j++) CPA16(st0 + (1 * 128 * G2_S) * 2 + j * 16, (const char*)(gA_L + j * 8));
        #pragma unroll
        for (int j = 0; j < 4; j++) CPA16(st0 + (2 * 128 * G2_S) * 2 + j * 16, (const char*)(gB_H + j * 8));
        #pragma unroll
        for (int j = 0; j < 4; j++) CPA16(st0 + (3 * 128 * G2_S) * 2 + j * 16, (const char*)(gB_L + j * 8));
        CPA_COMMIT();
    }

    for (int ch = 0; ch < nch; ch++) {
        CPA_WAIT0();
        __syncthreads();
        // prefetch chunk ch+1 into other stage
        if (ch + 1 < nch) {
            uint32_t stN = smem_base + ((ch + 1) & 1) * STAGE_BYTES + sRowOff;
            const __nv_bfloat16* pAH = gA_H + (ch + 1) * 64;
            const __nv_bfloat16* pAL = gA_L + (ch + 1) * 64;
            const __nv_bfloat16* pBH = gB_H + (ch + 1) * 64;
            const __nv_bfloat16* pBL = gB_L + (ch + 1) * 64;
            #pragma unroll
            for (int j = 0; j < 4; j++) {
                CPA16(stN + j * 16, (const char*)(pAH + j * 8));
                CPA16(stN + (1 * 128 * G2_S) * 2 + j * 16, (const char*)(pAL + j * 8));
                CPA16(stN + (2 * 128 * G2_S) * 2 + j * 16, (const char*)(pBH + j * 8));
                CPA16(stN + (3 * 128 * G2_S) * 2 + j * 16, (const char*)(pBL + j * 8));
            }
        }
        CPA_COMMIT();

        uint32_t stC = smem_base + (ch & 1) * STAGE_BYTES;
        uint32_t bAH = stC;
        uint32_t bAL = stC + (1 * 128 * G2_S) * 2;
        uint32_t bBH = stC + (2 * 128 * G2_S) * 2;
        uint32_t bBL = stC + (3 * 128 * G2_S) * 2;

        #pragma unroll
        for (int ks = 0; ks < 4; ks++) {
            int k0 = ks * 16;
            uint32_t bh[4][2], bl[4][2];
            #pragma unroll
            for (int p = 0; p < 2; p++) {
                uint32_t off = (uint32_t)((warp_n * 32 + p * 16 + bRowSel + lane7) * G2_S + k0 + bKSel) * 2;
                LDSM4(&bh[2 * p][0], bBH + off);
                LDSM4(&bl[2 * p][0], bBL + off);
            }
            #pragma unroll
            for (int mt = 0; mt < 4; mt++) {
                uint32_t off = (uint32_t)((warp_m * 64 + mt * 16 + aRowSel + lane7) * G2_S + k0 + aKSel) * 2;
                uint32_t ah[4], al[4];
                LDSM4(ah, bAH + off);
                LDSM4(al, bAL + off);
                #pragma unroll
                for (int nt = 0; nt < 4; nt++) {
                    MMA16816(acc[mt][nt], ah, bh[nt]);
                    MMA16816(acc[mt][nt], ah, bl[nt]);
                    MMA16816(acc[mt][nt], al, bh[nt]);
                }
            }
        }
    }

    // ---- epilogue ----
    int fr = lane >> 2;
    #pragma unroll
    for (int mt = 0; mt < 4; mt++) {
        int row0 = blockRow + warp_m * 64 + mt * 16 + fr;
        #pragma unroll
        for (int half = 0; half < 2; half++) {
            int row = row0 + half * 8;
            if (row >= M) continue;
            #pragma unroll
            for (int nt = 0; nt < 4; nt++) {
                int col = blockCol + warp_n * 32 + nt * 8 + ((lane & 3) * 2);
                float v0 = acc[mt][nt][half * 2];
                float v1 = acc[mt][nt][half * 2 + 1];
                if (bias) { v0 += bias[col]; v1 += bias[col + 1]; }
                if (mode == 0) {
                    *(float2*)&C[(size_t)row * N + col] = make_float2(v0, v1);
                } else if (mode == 1) {
                    float s1v = s1p[row], s2v = s2p[row];
                    const float* g = &Gx[(size_t)row * 384];
                    v0 += g[col] + s1v * g[col + 128] + s2v * g[col + 256];
                    v1 += g[col + 1] + s1v * g[col + 129] + s2v * g[col + 257];
                    v0 = fmaxf(v0, 0.f);
                    v1 = fmaxf(v1, 0.f);
                    size_t o = (size_t)row * 128 + col;
                    split2(v0, &outH[o], &outL[o]);
                    split2(v1, &outH[o + 1], &outL[o + 1]);
                } else {
                    v0 = (v0 > 0.f) ? v0 : 0.01f * v0;
                    v1 = (v1 > 0.f) ? v1 : 0.01f * v1;
                    size_t o = (size_t)row * 128 + col;
                    v0 += resid[o];
                    v1 += resid[o + 1];
                    *(float2*)&C[o] = make_float2(v0, v1);
                }
            }
        }
    }
}

// ---------------- launch ----------------
extern "C" void kernel_launch(void* const* d_in, const int* in_sizes, int n_in,
                              void* d_out, int out_size) {
    const float* h      = (const float*)d_in[0];
    const void*  esrc   = d_in[1];
    const void*  edst   = d_in[2];
    const float* W_pre  = (const float*)d_in[3];
    const float* b_pre  = (const float*)d_in[4];
    const float* W_post = (const float*)d_in[5];
    const float* b_post = (const float*)d_in[6];
    const float* W_mix  = (const float*)d_in[7];
    const float* b_mix  = (const float*)d_in[8];
    float* out = (float*)d_out;

    float *PQ, *G, *s1, *s2, *bias1;
    __nv_bfloat16 *hH, *hL, *aggH, *aggL, *hpH, *hpL;
    __nv_bfloat16 *B1Th, *B1Tl, *Wp0Th, *Wp0Tl, *WmixTh, *WmixTl, *WcatTh, *WcatTl;
    cudaGetSymbolAddress((void**)&PQ, g_PQ);
    cudaGetSymbolAddress((void**)&G, g_G);
    cudaGetSymbolAddress((void**)&s1, g_s1);
    cudaGetSymbolAddress((void**)&s2, g_s2);
    cudaGetSymbolAddress((void**)&bias1, g_bias1);
    cudaGetSymbolAddress((void**)&hH, g_hH);
    cudaGetSymbolAddress((void**)&hL, g_hL);
    cudaGetSymbolAddress((void**)&aggH, g_aggH);
    cudaGetSymbolAddress((void**)&aggL, g_aggL);
    cudaGetSymbolAddress((void**)&hpH, g_hpH);
    cudaGetSymbolAddress((void**)&hpL, g_hpL);
    cudaGetSymbolAddress((void**)&B1Th, g_B1Th);
    cudaGetSymbolAddress((void**)&B1Tl, g_B1Tl);
    cudaGetSymbolAddress((void**)&Wp0Th, g_Wp0Th);
    cudaGetSymbolAddress((void**)&Wp0Tl, g_Wp0Tl);
    cudaGetSymbolAddress((void**)&WmixTh, g_WmixTh);
    cudaGetSymbolAddress((void**)&WmixTl, g_WmixTl);
    cudaGetSymbolAddress((void**)&WcatTh, g_WcatTh);
    cudaGetSymbolAddress((void**)&WcatTl, g_WcatTl);

    static int smem_set = 0;
    if (!smem_set) {
        cudaFuncSetAttribute(tgemm_kernel, cudaFuncAttributeMaxDynamicSharedMemorySize, G2_SMEM_BYTES);
        smem_set = 1;
    }

    detect_kernel<<<1, 1>>>(edst);
    prep_kernel<<<768, 256>>>(W_pre, b_pre, W_post, W_mix);
    split_h_kernel<<<(NN * 128 / 4 + 255) / 256, 256>>>(h);
    hist_kernel<<<(NE + 255) / 256, 256>>>(edst);
    scanA_kernel<<<SCAN_BLOCKS, 1024>>>();
    scanB_kernel<<<1, 32>>>();
    scanC_kernel<<<SCAN_BLOCKS, 1024>>>();
    scatter_kernel<<<(NE + 255) / 256, 256>>>(esrc, edst);

    const int GB = (NN + 127) / 128;

    // GEMM1: PQ = h @ B1 (+bias1)   N=256, K=128
    tgemm_kernel<<<dim3(GB, 2), 256, G2_SMEM_BYTES>>>(
        hH, hL, B1Th, B1Tl, PQ, NN, 256, 128, 0,
        bias1, nullptr, nullptr, nullptr, nullptr, nullptr, nullptr);

    aggregate_kernel<<<NN, 128>>>();

    // GEMM2: G = agg @ Wcat   N=384, K=512
    tgemm_kernel<<<dim3(GB, 3), 256, G2_SMEM_BYTES>>>(
        aggH, aggL, WcatTh, WcatTl, G, NN, 384, 512, 0,
        nullptr, nullptr, nullptr, nullptr, nullptr, nullptr, nullptr);

    // GEMM3: hp = relu(h @ Wp0 + comb(G,s1,s2) + b_post) -> split bf16
    tgemm_kernel<<<dim3(GB, 1), 256, G2_SMEM_BYTES>>>(
        hH, hL, Wp0Th, Wp0Tl, nullptr, NN, 128, 128, 1,
        b_post, G, s1, s2, nullptr, hpH, hpL);

    // GEMM4: out = h + leaky_relu(hp @ W_mix + b_mix)
    tgemm_kernel<<<dim3(GB, 1), 256, G2_SMEM_BYTES>>>(
        hpH, hpL, WmixTh, WmixTl, out, NN, 128, 128, 2,
        b_mix, nullptr, nullptr, nullptr, h, nullptr, nullptr);
}

// round 8
// speedup vs baseline: 1.0530x; 1.0530x over previous
#include <cuda_runtime.h>
#include <cuda_fp16.h>
#include <math.h>
#include <stdint.h>

#define NN 50000
#define NE 600000
#define EPS_V 1e-5f
#define AVG_D_LOG 1.6094379124341003f

typedef unsigned long long u64;

// ---------------- scratch ----------------
__device__ float g_PQ[(size_t)NN * 256];            // [P | Q+b_pre]
__device__ __half g_hH[(size_t)NN * 128];           // h split hi (fp16)
__device__ __half g_hL[(size_t)NN * 128];           // h split lo
__device__ __half g_aggH[(size_t)NN * 512];
__device__ __half g_aggL[(size_t)NN * 512];
__device__ __half g_hpH[(size_t)NN * 128];
__device__ __half g_hpL[(size_t)NN * 128];
__device__ float g_G[(size_t)NN * 384];
__device__ float g_s1[NN];
__device__ float g_s2[NN];
__device__ int   g_count[NN];
__device__ int   g_offsets[NN + 1];
__device__ int   g_cursor[NN];
__device__ int   g_sorted_src[NE];
__device__ float g_bias1[256];
__device__ __half g_B1T[256 * 128];                 // B1^T fp16 (GEMM1 B)
__device__ __half g_Wp0T[128 * 128];                // W_post[0:128]^T fp16
__device__ __half g_WmixT[128 * 128];               // W_mix^T fp16
__device__ __half g_WcatT[384 * 512];               // Wcat^T fp16
__device__ int   g_blocksums[64];
__device__ int   g_blockoff[64];
__device__ int   g_is64;

// ---------------- helpers ----------------
__global__ void detect_kernel(const void* edst) {
    const int* v = (const int*)edst;
    g_is64 = (v[1] == 0 && v[3] == 0) ? 1 : 0;
}
__device__ __forceinline__ int edge_index(const void* p, int i) {
    if (g_is64) return (int)(((const long long*)p)[i]);
    return ((const int*)p)[i];
}
__device__ __forceinline__ void split2h(float v, __half* hi, __half* lo) {
    __half h = __float2half_rn(v);
    *hi = h;
    *lo = __float2half_rn(v - __half2float(h));
}

// ---------------- prep ----------------
__global__ void prep_kernel(const float* __restrict__ W_pre,
                            const float* __restrict__ b_pre,
                            const float* __restrict__ W_post,
                            const float* __restrict__ W_mix) {
    int idx = blockIdx.x * blockDim.x + threadIdx.x;
    if (idx < NN) g_count[idx] = 0;
    if (idx < 256) g_bias1[idx] = (idx < 128) ? 0.f : b_pre[idx - 128];
    if (idx < 256 * 128) {
        int n = idx >> 7, k = idx & 127;
        float v = (n < 128) ? W_pre[k * 128 + n] : W_pre[(128 + k) * 128 + (n - 128)];
        g_B1T[idx] = __float2half_rn(v);
    }
    if (idx < 128 * 128) {
        int n = idx >> 7, k = idx & 127;
        g_Wp0T[idx]  = __float2half_rn(W_post[k * 128 + n]);
        g_WmixT[idx] = __float2half_rn(W_mix[k * 128 + n]);
    }
    if (idx < 384 * 512) {
        int n = idx >> 9, k = idx & 511;
        int grp = n >> 7, jj = n & 127;
        g_WcatT[idx] = __float2half_rn(W_post[(size_t)(128 + grp * 512 + k) * 128 + jj]);
    }
}

__global__ void __launch_bounds__(256) split_h_kernel(const float* __restrict__ h) {
    int i = blockIdx.x * blockDim.x + threadIdx.x;
    int idx = i * 4;
    if (idx < NN * 128) {
        float4 v = *(const float4*)(h + idx);
        float vv[4] = {v.x, v.y, v.z, v.w};
        #pragma unroll
        for (int j = 0; j < 4; j++)
            split2h(vv[j], &g_hH[idx + j], &g_hL[idx + j]);
    }
}

// ---------------- histogram / scan / scatter ----------------
__global__ void hist_kernel(const void* __restrict__ edst) {
    int e = blockIdx.x * blockDim.x + threadIdx.x;
    if (e < NE) atomicAdd(&g_count[edge_index(edst, e)], 1);
}

#define SCAN_BLOCKS ((NN + 1023) / 1024)

__global__ void __launch_bounds__(1024) scanA_kernel() {
    __shared__ int sdata[1024];
    int tid = threadIdx.x;
    int i = blockIdx.x * 1024 + tid;
    int v = (i < NN) ? g_count[i] : 0;
    sdata[tid] = v;
    __syncthreads();
    #pragma unroll
    for (int off = 1; off < 1024; off <<= 1) {
        int t = (tid >= off) ? sdata[tid - off] : 0;
        __syncthreads();
        sdata[tid] += t;
        __syncthreads();
    }
    if (i < NN) g_offsets[i] = sdata[tid] - v;
    if (tid == 1023) g_blocksums[blockIdx.x] = sdata[1023];
}
__global__ void scanB_kernel() {
    if (threadIdx.x == 0) {
        int run = 0;
        for (int b = 0; b < SCAN_BLOCKS; b++) { g_blockoff[b] = run; run += g_blocksums[b]; }
    }
}
__global__ void __launch_bounds__(1024) scanC_kernel() {
    int i = blockIdx.x * 1024 + threadIdx.x;
    if (i < NN) {
        int o = g_offsets[i] + g_blockoff[blockIdx.x];
        g_offsets[i] = o;
        g_cursor[i] = o;
    }
    if (i == 0) g_offsets[NN] = NE;
}

__global__ void scatter_kernel(const void* __restrict__ esrc, const void* __restrict__ edst) {
    int e = blockIdx.x * blockDim.x + threadIdx.x;
    if (e < NE) {
        int d = edge_index(edst, e);
        int s = edge_index(esrc, e);
        g_sorted_src[atomicAdd(&g_cursor[d], 1)] = s;
    }
}

// ---------------- aggregate ----------------
__global__ void __launch_bounds__(128) aggregate_kernel() {
    int n = blockIdx.x;
    int d = threadIdx.x;
    int start = g_offsets[n];
    int end = g_offsets[n + 1];
    float qd = g_PQ[(size_t)n * 256 + 128 + d];
    float s0 = 0.f, sq0 = 0.f, s1a = 0.f, sq1 = 0.f;
    float mx = -3.4e38f, mn = 3.4e38f;
    int i = start;
    for (; i + 1 < end; i += 2) {
        int sa = g_sorted_src[i];
        int sb = g_sorted_src[i + 1];
        float va = fmaxf(g_PQ[(size_t)sa * 256 + d] + qd, 0.f);
        float vb = fmaxf(g_PQ[(size_t)sb * 256 + d] + qd, 0.f);
        s0 += va; sq0 += va * va;
        s1a += vb; sq1 += vb * vb;
        mx = fmaxf(mx, fmaxf(va, vb));
        mn = fminf(mn, fminf(va, vb));
    }
    if (i < end) {
        int sa = g_sorted_src[i];
        float va = fmaxf(g_PQ[(size_t)sa * 256 + d] + qd, 0.f);
        s0 += va; sq0 += va * va;
        mx = fmaxf(mx, va); mn = fminf(mn, va);
    }
    float s = s0 + s1a, sq = sq0 + sq1;
    float degf = (float)(end - start);
    float inv = 1.f / degf;
    float mean = s * inv;
    float var = fmaxf(sq * inv - mean * mean, 0.f);
    float sd = sqrtf(var + EPS_V);
    size_t base = (size_t)n * 512;
    float vals[4] = {mean, mx, mn, sd};
    #pragma unroll
    for (int t = 0; t < 4; t++)
        split2h(vals[t], &g_aggH[base + t * 128 + d], &g_aggL[base + t * 128 + d]);
    if (d == 0) {
        float ld = logf(degf + 1.f);
        g_s1[n] = ld / AVG_D_LOG;
        g_s2[n] = AVG_D_LOG / ld;
    }
}

// ---------------- fp16-split mma.sync GEMM: D = AhB + AlB ----------------
#define MMA16816(c, a, b) \
    asm volatile("mma.sync.aligned.m16n8k16.row.col.f32.f16.f16.f32 " \
        "{%0,%1,%2,%3}, {%4,%5,%6,%7}, {%8,%9}, {%0,%1,%2,%3};" \
        : "+f"((c)[0]), "+f"((c)[1]), "+f"((c)[2]), "+f"((c)[3]) \
        : "r"((a)[0]), "r"((a)[1]), "r"((a)[2]), "r"((a)[3]), \
          "r"((b)[0]), "r"((b)[1]))

#define LDSM4(r, a) \
    asm volatile("ldmatrix.sync.aligned.m8n8.x4.shared.b16 {%0,%1,%2,%3}, [%4];" \
        : "=r"((r)[0]), "=r"((r)[1]), "=r"((r)[2]), "=r"((r)[3]) : "r"(a))

#define CPA16(dst, src) asm volatile("cp.async.ca.shared.global [%0], [%1], 16;" :: "r"(dst), "l"(src))
#define CPA_COMMIT()    asm volatile("cp.async.commit_group;" ::: "memory")
#define CPA_WAIT0()     asm volatile("cp.async.wait_group 0;" ::: "memory")

#define G2_S 72
#define ARR_BYTES (128 * G2_S * 2)                  // one operand array
#define STAGE_BYTES (3 * ARR_BYTES)                 // AH, AL, BH
#define G2_SMEM_BYTES (2 * STAGE_BYTES)             // 110592

__global__ void __launch_bounds__(256) tgemm_kernel(
    const __half* __restrict__ aHp, const __half* __restrict__ aLp,
    const __half* __restrict__ bp,
    float* __restrict__ C, int M, int N, int K, int mode,
    const float* __restrict__ bias, const float* __restrict__ Gx,
    const float* __restrict__ s1p, const float* __restrict__ s2p,
    const float* __restrict__ resid,
    __half* __restrict__ outH, __half* __restrict__ outL)
{
    extern __shared__ __half sm[];
    uint32_t smem_base = (uint32_t)__cvta_generic_to_shared(sm);

    int tid = threadIdx.x, lane = tid & 31, wid = tid >> 5;
    int warp_m = wid >> 2;
    int warp_n = wid & 3;
    int blockRow = blockIdx.x * 128, blockCol = blockIdx.y * 128;

    float acc[4][4][4];
    #pragma unroll
    for (int i = 0; i < 4; i++)
        #pragma unroll
        for (int j = 0; j < 4; j++)
            #pragma unroll
            for (int q = 0; q < 4; q++) acc[i][j][q] = 0.f;

    // global->smem loader mapping
    int ldRow = tid >> 1, ldHalf = tid & 1;
    int aRow = blockRow + ldRow; if (aRow > M - 1) aRow = M - 1;
    const __half* gA_H = aHp + (size_t)aRow * K + ldHalf * 32;
    const __half* gA_L = aLp + (size_t)aRow * K + ldHalf * 32;
    const __half* gB   = bp + (size_t)(blockCol + ldRow) * K + ldHalf * 32;
    uint32_t sRowOff = (uint32_t)(ldRow * G2_S + ldHalf * 32) * 2;

    // ldmatrix per-lane address components
    int lane7 = lane & 7;
    int aRowSel = ((lane >> 3) & 1) * 8;
    int aKSel   = ((lane >> 4) & 1) * 8;
    int bRowSel = ((lane >> 4) & 1) * 8;
    int bKSel   = ((lane >> 3) & 1) * 8;

    int nch = K >> 6;

    // prologue: chunk 0 -> stage 0
    {
        uint32_t st0 = smem_base + sRowOff;
        #pragma unroll
        for (int j = 0; j < 4; j++) {
            CPA16(st0 + j * 16, (const char*)(gA_H + j * 8));
            CPA16(st0 + ARR_BYTES + j * 16, (const char*)(gA_L + j * 8));
            CPA16(st0 + 2 * ARR_BYTES + j * 16, (const char*)(gB + j * 8));
        }
        CPA_COMMIT();
    }

    for (int ch = 0; ch < nch; ch++) {
        CPA_WAIT0();
        __syncthreads();
        if (ch + 1 < nch) {
            uint32_t stN = smem_base + ((ch + 1) & 1) * STAGE_BYTES + sRowOff;
            const __half* pAH = gA_H + (ch + 1) * 64;
            const __half* pAL = gA_L + (ch + 1) * 64;
            const __half* pB  = gB + (ch + 1) * 64;
            #pragma unroll
            for (int j = 0; j < 4; j++) {
                CPA16(stN + j * 16, (const char*)(pAH + j * 8));
                CPA16(stN + ARR_BYTES + j * 16, (const char*)(pAL + j * 8));
                CPA16(stN + 2 * ARR_BYTES + j * 16, (const char*)(pB + j * 8));
            }
        }
        CPA_COMMIT();

        uint32_t stC = smem_base + (ch & 1) * STAGE_BYTES;
        uint32_t bAH = stC;
        uint32_t bAL = stC + ARR_BYTES;
        uint32_t bB  = stC + 2 * ARR_BYTES;

        #pragma unroll
        for (int ks = 0; ks < 4; ks++) {
            int k0 = ks * 16;
            uint32_t bh[4][2];
            #pragma unroll
            for (int p = 0; p < 2; p++) {
                uint32_t off = (uint32_t)((warp_n * 32 + p * 16 + bRowSel + lane7) * G2_S + k0 + bKSel) * 2;
                LDSM4(&bh[2 * p][0], bB + off);
            }
            #pragma unroll
            for (int mt = 0; mt < 4; mt++) {
                uint32_t off = (uint32_t)((warp_m * 64 + mt * 16 + aRowSel + lane7) * G2_S + k0 + aKSel) * 2;
                uint32_t ah[4], al[4];
                LDSM4(ah, bAH + off);
                LDSM4(al, bAL + off);
                #pragma unroll
                for (int nt = 0; nt < 4; nt++) {
                    MMA16816(acc[mt][nt], ah, bh[nt]);
                    MMA16816(acc[mt][nt], al, bh[nt]);
                }
            }
        }
    }

    // epilogue
    int fr = lane >> 2;
    #pragma unroll
    for (int mt = 0; mt < 4; mt++) {
        int row0 = blockRow + warp_m * 64 + mt * 16 + fr;
        #pragma unroll
        for (int half = 0; half < 2; half++) {
            int row = row0 + half * 8;
            if (row >= M) continue;
            #pragma unroll
            for (int nt = 0; nt < 4; nt++) {
                int col = blockCol + warp_n * 32 + nt * 8 + ((lane & 3) * 2);
                float v0 = acc[mt][nt][half * 2];
                float v1 = acc[mt][nt][half * 2 + 1];
                if (bias) { v0 += bias[col]; v1 += bias[col + 1]; }
                if (mode == 0) {
                    *(float2*)&C[(size_t)row * N + col] = make_float2(v0, v1);
                } else if (mode == 1) {
                    float s1v = s1p[row], s2v = s2p[row];
                    const float* g = &Gx[(size_t)row * 384];
                    v0 += g[col] + s1v * g[col + 128] + s2v * g[col + 256];
                    v1 += g[col + 1] + s1v * g[col + 129] + s2v * g[col + 257];
                    v0 = fmaxf(v0, 0.f);
                    v1 = fmaxf(v1, 0.f);
                    size_t o = (size_t)row * 128 + col;
                    split2h(v0, &outH[o], &outL[o]);
                    split2h(v1, &outH[o + 1], &outL[o + 1]);
                } else {
                    v0 = (v0 > 0.f) ? v0 : 0.01f * v0;
                    v1 = (v1 > 0.f) ? v1 : 0.01f * v1;
                    size_t o = (size_t)row * 128 + col;
                    v0 += resid[o];
                    v1 += resid[o + 1];
                    *(float2*)&C[o] = make_float2(v0, v1);
                }
            }
        }
    }
}

// ---------------- launch ----------------
extern "C" void kernel_launch(void* const* d_in, const int* in_sizes, int n_in,
                              void* d_out, int out_size) {
    const float* h      = (const float*)d_in[0];
    const void*  esrc   = d_in[1];
    const void*  edst   = d_in[2];
    const float* W_pre  = (const float*)d_in[3];
    const float* b_pre  = (const float*)d_in[4];
    const float* W_post = (const float*)d_in[5];
    const float* b_post = (const float*)d_in[6];
    const float* W_mix  = (const float*)d_in[7];
    const float* b_mix  = (const float*)d_in[8];
    float* out = (float*)d_out;

    float *PQ, *G, *s1, *s2, *bias1;
    __half *hH, *hL, *aggH, *aggL, *hpH, *hpL;
    __half *B1T, *Wp0T, *WmixT, *WcatT;
    cudaGetSymbolAddress((void**)&PQ, g_PQ);
    cudaGetSymbolAddress((void**)&G, g_G);
    cudaGetSymbolAddress((void**)&s1, g_s1);
    cudaGetSymbolAddress((void**)&s2, g_s2);
    cudaGetSymbolAddress((void**)&bias1, g_bias1);
    cudaGetSymbolAddress((void**)&hH, g_hH);
    cudaGetSymbolAddress((void**)&hL, g_hL);
    cudaGetSymbolAddress((void**)&aggH, g_aggH);
    cudaGetSymbolAddress((void**)&aggL, g_aggL);
    cudaGetSymbolAddress((void**)&hpH, g_hpH);
    cudaGetSymbolAddress((void**)&hpL, g_hpL);
    cudaGetSymbolAddress((void**)&B1T, g_B1T);
    cudaGetSymbolAddress((void**)&Wp0T, g_Wp0T);
    cudaGetSymbolAddress((void**)&WmixT, g_WmixT);
    cudaGetSymbolAddress((void**)&WcatT, g_WcatT);

    static int smem_set = 0;
    if (!smem_set) {
        cudaFuncSetAttribute(tgemm_kernel, cudaFuncAttributeMaxDynamicSharedMemorySize, G2_SMEM_BYTES);
        smem_set = 1;
    }

    detect_kernel<<<1, 1>>>(edst);
    prep_kernel<<<768, 256>>>(W_pre, b_pre, W_post, W_mix);
    split_h_kernel<<<(NN * 128 / 4 + 255) / 256, 256>>>(h);
    hist_kernel<<<(NE + 255) / 256, 256>>>(edst);
    scanA_kernel<<<SCAN_BLOCKS, 1024>>>();
    scanB_kernel<<<1, 32>>>();
    scanC_kernel<<<SCAN_BLOCKS, 1024>>>();
    scatter_kernel<<<(NE + 255) / 256, 256>>>(esrc, edst);

    const int GB = (NN + 127) / 128;

    // GEMM1: PQ = h @ B1 (+bias1)   N=256, K=128
    tgemm_kernel<<<dim3(GB, 2), 256, G2_SMEM_BYTES>>>(
        hH, hL, B1T, PQ, NN, 256, 128, 0,
        bias1, nullptr, nullptr, nullptr, nullptr, nullptr, nullptr);

    aggregate_kernel<<<NN, 128>>>();

    // GEMM2: G = agg @ Wcat   N=384, K=512
    tgemm_kernel<<<dim3(GB, 3), 256, G2_SMEM_BYTES>>>(
        aggH, aggL, WcatT, G, NN, 384, 512, 0,
        nullptr, nullptr, nullptr, nullptr, nullptr, nullptr, nullptr);

    // GEMM3: hp = relu(h @ Wp0 + comb(G,s1,s2) + b_post) -> split fp16
    tgemm_kernel<<<dim3(GB, 1), 256, G2_SMEM_BYTES>>>(
        hH, hL, Wp0T, nullptr, NN, 128, 128, 1,
        b_post, G, s1, s2, nullptr, hpH, hpL);

    // GEMM4: out = h + leaky_relu(hp @ W_mix + b_mix)
    tgemm_kernel<<<dim3(GB, 1), 256, G2_SMEM_BYTES>>>(
        hpH, hpL, WmixT, out, NN, 128, 128, 2,
        b_mix, nullptr, nullptr, nullptr, h, nullptr, nullptr);
}

// round 9
// speedup vs baseline: 1.2998x; 1.2343x over previous
#include <cuda_runtime.h>
#include <cuda_fp16.h>
#include <math.h>
#include <stdint.h>

#define NN 50000
#define NE 600000
#define EPS_V 1e-5f
#define AVG_D_LOG 1.6094379124341003f

typedef unsigned long long u64;

// ---------------- scratch ----------------
__device__ float g_PQ[(size_t)NN * 256];            // [P | Q+b_pre]
__device__ __half g_hH[(size_t)NN * 128];           // h split hi
__device__ __half g_hL[(size_t)NN * 128];           // h split lo
__device__ __half g_agg[(size_t)NN * 512];          // agg fp16 (single)
__device__ __half g_hpH[(size_t)NN * 128];
__device__ __half g_hpL[(size_t)NN * 128];
__device__ __half g_G[(size_t)NN * 384];            // agg @ Wcat, fp16
__device__ float g_s1[NN];
__device__ float g_s2[NN];
__device__ int   g_count[NN];
__device__ int   g_offsets[NN + 1];
__device__ int   g_cursor[NN];
__device__ int   g_sorted_src[NE];
__device__ float g_bias1[256];
__device__ __half g_B1T[256 * 128];
__device__ __half g_Wp0T[128 * 128];
__device__ __half g_WmixT[128 * 128];
__device__ __half g_WcatT[384 * 512];
__device__ int   g_blocksums[64];
__device__ int   g_blockoff[64];
__device__ int   g_is64;

// ---------------- helpers ----------------
__global__ void detect_kernel(const void* edst) {
    const int* v = (const int*)edst;
    g_is64 = (v[1] == 0 && v[3] == 0) ? 1 : 0;
}
__device__ __forceinline__ int edge_index(const void* p, int i) {
    if (g_is64) return (int)(((const long long*)p)[i]);
    return ((const int*)p)[i];
}
__device__ __forceinline__ void split2h(float v, __half* hi, __half* lo) {
    __half h = __float2half_rn(v);
    *hi = h;
    *lo = __float2half_rn(v - __half2float(h));
}

// ---------------- prep ----------------
__global__ void prep_kernel(const float* __restrict__ W_pre,
                            const float* __restrict__ b_pre,
                            const float* __restrict__ W_post,
                            const float* __restrict__ W_mix) {
    int idx = blockIdx.x * blockDim.x + threadIdx.x;
    if (idx < NN) g_count[idx] = 0;
    if (idx < 256) g_bias1[idx] = (idx < 128) ? 0.f : b_pre[idx - 128];
    if (idx < 256 * 128) {
        int n = idx >> 7, k = idx & 127;
        float v = (n < 128) ? W_pre[k * 128 + n] : W_pre[(128 + k) * 128 + (n - 128)];
        g_B1T[idx] = __float2half_rn(v);
    }
    if (idx < 128 * 128) {
        int n = idx >> 7, k = idx & 127;
        g_Wp0T[idx]  = __float2half_rn(W_post[k * 128 + n]);
        g_WmixT[idx] = __float2half_rn(W_mix[k * 128 + n]);
    }
    if (idx < 384 * 512) {
        int n = idx >> 9, k = idx & 511;
        int grp = n >> 7, jj = n & 127;
        g_WcatT[idx] = __float2half_rn(W_post[(size_t)(128 + grp * 512 + k) * 128 + jj]);
    }
}

__global__ void __launch_bounds__(256) split_h_kernel(const float* __restrict__ h) {
    int i = blockIdx.x * blockDim.x + threadIdx.x;
    int idx = i * 4;
    if (idx < NN * 128) {
        float4 v = *(const float4*)(h + idx);
        float vv[4] = {v.x, v.y, v.z, v.w};
        #pragma unroll
        for (int j = 0; j < 4; j++)
            split2h(vv[j], &g_hH[idx + j], &g_hL[idx + j]);
    }
}

// ---------------- histogram / scan / scatter ----------------
__global__ void hist_kernel(const void* __restrict__ edst) {
    int e = blockIdx.x * blockDim.x + threadIdx.x;
    if (e < NE) atomicAdd(&g_count[edge_index(edst, e)], 1);
}

#define SCAN_BLOCKS ((NN + 1023) / 1024)

__global__ void __launch_bounds__(1024) scanA_kernel() {
    __shared__ int sdata[1024];
    int tid = threadIdx.x;
    int i = blockIdx.x * 1024 + tid;
    int v = (i < NN) ? g_count[i] : 0;
    sdata[tid] = v;
    __syncthreads();
    #pragma unroll
    for (int off = 1; off < 1024; off <<= 1) {
        int t = (tid >= off) ? sdata[tid - off] : 0;
        __syncthreads();
        sdata[tid] += t;
        __syncthreads();
    }
    if (i < NN) g_offsets[i] = sdata[tid] - v;
    if (tid == 1023) g_blocksums[blockIdx.x] = sdata[1023];
}
__global__ void scanB_kernel() {
    if (threadIdx.x == 0) {
        int run = 0;
        for (int b = 0; b < SCAN_BLOCKS; b++) { g_blockoff[b] = run; run += g_blocksums[b]; }
    }
}
__global__ void __launch_bounds__(1024) scanC_kernel() {
    int i = blockIdx.x * 1024 + threadIdx.x;
    if (i < NN) {
        int o = g_offsets[i] + g_blockoff[blockIdx.x];
        g_offsets[i] = o;
        g_cursor[i] = o;
    }
    if (i == 0) g_offsets[NN] = NE;
}

__global__ void scatter_kernel(const void* __restrict__ esrc, const void* __restrict__ edst) {
    int e = blockIdx.x * blockDim.x + threadIdx.x;
    if (e < NE) {
        int d = edge_index(edst, e);
        int s = edge_index(esrc, e);
        g_sorted_src[atomicAdd(&g_cursor[d], 1)] = s;
    }
}

// ---------------- aggregate (writes single fp16 agg) ----------------
__global__ void __launch_bounds__(128) aggregate_kernel() {
    int n = blockIdx.x;
    int d = threadIdx.x;
    int start = g_offsets[n];
    int end = g_offsets[n + 1];
    float qd = g_PQ[(size_t)n * 256 + 128 + d];
    float s0 = 0.f, sq0 = 0.f, s1a = 0.f, sq1 = 0.f;
    float mx = -3.4e38f, mn = 3.4e38f;
    int i = start;
    for (; i + 1 < end; i += 2) {
        int sa = g_sorted_src[i];
        int sb = g_sorted_src[i + 1];
        float va = fmaxf(g_PQ[(size_t)sa * 256 + d] + qd, 0.f);
        float vb = fmaxf(g_PQ[(size_t)sb * 256 + d] + qd, 0.f);
        s0 += va; sq0 += va * va;
        s1a += vb; sq1 += vb * vb;
        mx = fmaxf(mx, fmaxf(va, vb));
        mn = fminf(mn, fminf(va, vb));
    }
    if (i < end) {
        int sa = g_sorted_src[i];
        float va = fmaxf(g_PQ[(size_t)sa * 256 + d] + qd, 0.f);
        s0 += va; sq0 += va * va;
        mx = fmaxf(mx, va); mn = fminf(mn, va);
    }
    float s = s0 + s1a, sq = sq0 + sq1;
    float degf = (float)(end - start);
    float inv = 1.f / degf;
    float mean = s * inv;
    float var = fmaxf(sq * inv - mean * mean, 0.f);
    float sd = sqrtf(var + EPS_V);
    size_t base = (size_t)n * 512;
    g_agg[base + d]       = __float2half_rn(mean);
    g_agg[base + 128 + d] = __float2half_rn(mx);
    g_agg[base + 256 + d] = __float2half_rn(mn);
    g_agg[base + 384 + d] = __float2half_rn(sd);
    if (d == 0) {
        float ld = logf(degf + 1.f);
        g_s1[n] = ld / AVG_D_LOG;
        g_s2[n] = AVG_D_LOG / ld;
    }
}

// ---------------- fp16(-split) mma.sync GEMM ----------------
// D = Ah*B (+ Al*B if useAl). Grid is 1-D: bid -> (xt = bid/nY, yt = bid%nY)
// so same-A blocks are co-scheduled (L2 sharing).
// mode 0: write C fp32, or Ch fp16 when Ch != nullptr (+bias)
// mode 1: v = relu(acc + bias + G0 + s1*G1 + s2*G2) with G fp16; write split to outH/outL (N=128)
// mode 2: C = resid + leaky_relu(acc + bias)  (N=128)

#define MMA16816(c, a, b) \
    asm volatile("mma.sync.aligned.m16n8k16.row.col.f32.f16.f16.f32 " \
        "{%0,%1,%2,%3}, {%4,%5,%6,%7}, {%8,%9}, {%0,%1,%2,%3};" \
        : "+f"((c)[0]), "+f"((c)[1]), "+f"((c)[2]), "+f"((c)[3]) \
        : "r"((a)[0]), "r"((a)[1]), "r"((a)[2]), "r"((a)[3]), \
          "r"((b)[0]), "r"((b)[1]))

#define LDSM4(r, a) \
    asm volatile("ldmatrix.sync.aligned.m8n8.x4.shared.b16 {%0,%1,%2,%3}, [%4];" \
        : "=r"((r)[0]), "=r"((r)[1]), "=r"((r)[2]), "=r"((r)[3]) : "r"(a))

#define CPA16(dst, src) asm volatile("cp.async.ca.shared.global [%0], [%1], 16;" :: "r"(dst), "l"(src))
#define CPA_COMMIT()    asm volatile("cp.async.commit_group;" ::: "memory")
#define CPA_WAIT0()     asm volatile("cp.async.wait_group 0;" ::: "memory")

#define G2_S 72
#define ARR_BYTES (128 * G2_S * 2)
#define STAGE_BYTES (3 * ARR_BYTES)
#define G2_SMEM_BYTES (2 * STAGE_BYTES)             // 110592

__global__ void __launch_bounds__(256) tgemm_kernel(
    const __half* __restrict__ aHp, const __half* __restrict__ aLp,
    const __half* __restrict__ bp,
    float* __restrict__ C, __half* __restrict__ Ch,
    int M, int N, int K, int mode, int useAl, int nY,
    const float* __restrict__ bias, const __half* __restrict__ Gx,
    const float* __restrict__ s1p, const float* __restrict__ s2p,
    const float* __restrict__ resid,
    __half* __restrict__ outH, __half* __restrict__ outL)
{
    extern __shared__ __half sm[];
    uint32_t smem_base = (uint32_t)__cvta_generic_to_shared(sm);

    int tid = threadIdx.x, lane = tid & 31, wid = tid >> 5;
    int warp_m = wid >> 2;
    int warp_n = wid & 3;
    int bid = blockIdx.x;
    int blockRow = (bid / nY) * 128, blockCol = (bid % nY) * 128;

    float acc[4][4][4];
    #pragma unroll
    for (int i = 0; i < 4; i++)
        #pragma unroll
        for (int j = 0; j < 4; j++)
            #pragma unroll
            for (int q = 0; q < 4; q++) acc[i][j][q] = 0.f;

    int ldRow = tid >> 1, ldHalf = tid & 1;
    int aRow = blockRow + ldRow; if (aRow > M - 1) aRow = M - 1;
    const __half* gA_H = aHp + (size_t)aRow * K + ldHalf * 32;
    const __half* gA_L = useAl ? (aLp + (size_t)aRow * K + ldHalf * 32) : nullptr;
    const __half* gB   = bp + (size_t)(blockCol + ldRow) * K + ldHalf * 32;
    uint32_t sRowOff = (uint32_t)(ldRow * G2_S + ldHalf * 32) * 2;

    int lane7 = lane & 7;
    int aRowSel = ((lane >> 3) & 1) * 8;
    int aKSel   = ((lane >> 4) & 1) * 8;
    int bRowSel = ((lane >> 4) & 1) * 8;
    int bKSel   = ((lane >> 3) & 1) * 8;

    int nch = K >> 6;

    {
        uint32_t st0 = smem_base + sRowOff;
        #pragma unroll
        for (int j = 0; j < 4; j++) {
            CPA16(st0 + j * 16, (const char*)(gA_H + j * 8));
            if (useAl) CPA16(st0 + ARR_BYTES + j * 16, (const char*)(gA_L + j * 8));
            CPA16(st0 + 2 * ARR_BYTES + j * 16, (const char*)(gB + j * 8));
        }
        CPA_COMMIT();
    }

    for (int ch = 0; ch < nch; ch++) {
        CPA_WAIT0();
        __syncthreads();
        if (ch + 1 < nch) {
            uint32_t stN = smem_base + ((ch + 1) & 1) * STAGE_BYTES + sRowOff;
            const __half* pAH = gA_H + (ch + 1) * 64;
            const __half* pB  = gB + (ch + 1) * 64;
            #pragma unroll
            for (int j = 0; j < 4; j++) {
                CPA16(stN + j * 16, (const char*)(pAH + j * 8));
                if (useAl) CPA16(stN + ARR_BYTES + j * 16, (const char*)(gA_L + (ch + 1) * 64 + j * 8));
                CPA16(stN + 2 * ARR_BYTES + j * 16, (const char*)(pB + j * 8));
            }
        }
        CPA_COMMIT();

        uint32_t stC = smem_base + (ch & 1) * STAGE_BYTES;
        uint32_t bAH = stC;
        uint32_t bAL = stC + ARR_BYTES;
        uint32_t bB  = stC + 2 * ARR_BYTES;

        #pragma unroll
        for (int ks = 0; ks < 4; ks++) {
            int k0 = ks * 16;
            uint32_t bh[4][2];
            #pragma unroll
            for (int p = 0; p < 2; p++) {
                uint32_t off = (uint32_t)((warp_n * 32 + p * 16 + bRowSel + lane7) * G2_S + k0 + bKSel) * 2;
                LDSM4(&bh[2 * p][0], bB + off);
            }
            #pragma unroll
            for (int mt = 0; mt < 4; mt++) {
                uint32_t off = (uint32_t)((warp_m * 64 + mt * 16 + aRowSel + lane7) * G2_S + k0 + aKSel) * 2;
                uint32_t ah[4];
                LDSM4(ah, bAH + off);
                #pragma unroll
                for (int nt = 0; nt < 4; nt++)
                    MMA16816(acc[mt][nt], ah, bh[nt]);
                if (useAl) {
                    uint32_t al[4];
                    LDSM4(al, bAL + off);
                    #pragma unroll
                    for (int nt = 0; nt < 4; nt++)
                        MMA16816(acc[mt][nt], al, bh[nt]);
                }
            }
        }
    }

    // epilogue
    int fr = lane >> 2;
    #pragma unroll
    for (int mt = 0; mt < 4; mt++) {
        int row0 = blockRow + warp_m * 64 + mt * 16 + fr;
        #pragma unroll
        for (int half = 0; half < 2; half++) {
            int row = row0 + half * 8;
            if (row >= M) continue;
            #pragma unroll
            for (int nt = 0; nt < 4; nt++) {
                int col = blockCol + warp_n * 32 + nt * 8 + ((lane & 3) * 2);
                float v0 = acc[mt][nt][half * 2];
                float v1 = acc[mt][nt][half * 2 + 1];
                if (bias) { v0 += bias[col]; v1 += bias[col + 1]; }
                if (mode == 0) {
                    if (Ch) {
                        __half2 hv = __floats2half2_rn(v0, v1);
                        *(__half2*)&Ch[(size_t)row * N + col] = hv;
                    } else {
                        *(float2*)&C[(size_t)row * N + col] = make_float2(v0, v1);
                    }
                } else if (mode == 1) {
                    float s1v = s1p[row], s2v = s2p[row];
                    const __half* g = &Gx[(size_t)row * 384];
                    float2 g0 = __half22float2(*(const __half2*)&g[col]);
                    float2 g1 = __half22float2(*(const __half2*)&g[col + 128]);
                    float2 g2 = __half22float2(*(const __half2*)&g[col + 256]);
                    v0 += g0.x + s1v * g1.x + s2v * g2.x;
                    v1 += g0.y + s1v * g1.y + s2v * g2.y;
                    v0 = fmaxf(v0, 0.f);
                    v1 = fmaxf(v1, 0.f);
                    size_t o = (size_t)row * 128 + col;
                    split2h(v0, &outH[o], &outL[o]);
                    split2h(v1, &outH[o + 1], &outL[o + 1]);
                } else {
                    v0 = (v0 > 0.f) ? v0 : 0.01f * v0;
                    v1 = (v1 > 0.f) ? v1 : 0.01f * v1;
                    size_t o = (size_t)row * 128 + col;
                    v0 += resid[o];
                    v1 += resid[o + 1];
                    *(float2*)&C[o] = make_float2(v0, v1);
                }
            }
        }
    }
}

// ---------------- launch ----------------
extern "C" void kernel_launch(void* const* d_in, const int* in_sizes, int n_in,
                              void* d_out, int out_size) {
    const float* h      = (const float*)d_in[0];
    const void*  esrc   = d_in[1];
    const void*  edst   = d_in[2];
    const float* W_pre  = (const float*)d_in[3];
    const float* b_pre  = (const float*)d_in[4];
    const float* W_post = (const float*)d_in[5];
    const float* b_post = (const float*)d_in[6];
    const float* W_mix  = (const float*)d_in[7];
    const float* b_mix  = (const float*)d_in[8];
    float* out = (float*)d_out;

    float *PQ, *s1, *s2, *bias1;
    __half *hH, *hL, *agg, *hpH, *hpL, *G;
    __half *B1T, *Wp0T, *WmixT, *WcatT;
    cudaGetSymbolAddress((void**)&PQ, g_PQ);
    cudaGetSymbolAddress((void**)&G, g_G);
    cudaGetSymbolAddress((void**)&s1, g_s1);
    cudaGetSymbolAddress((void**)&s2, g_s2);
    cudaGetSymbolAddress((void**)&bias1, g_bias1);
    cudaGetSymbolAddress((void**)&hH, g_hH);
    cudaGetSymbolAddress((void**)&hL, g_hL);
    cudaGetSymbolAddress((void**)&agg, g_agg);
    cudaGetSymbolAddress((void**)&hpH, g_hpH);
    cudaGetSymbolAddress((void**)&hpL, g_hpL);
    cudaGetSymbolAddress((void**)&B1T, g_B1T);
    cudaGetSymbolAddress((void**)&Wp0T, g_Wp0T);
    cudaGetSymbolAddress((void**)&WmixT, g_WmixT);
    cudaGetSymbolAddress((void**)&WcatT, g_WcatT);

    static int smem_set = 0;
    if (!smem_set) {
        cudaFuncSetAttribute(tgemm_kernel, cudaFuncAttributeMaxDynamicSharedMemorySize, G2_SMEM_BYTES);
        smem_set = 1;
    }

    detect_kernel<<<1, 1>>>(edst);
    prep_kernel<<<768, 256>>>(W_pre, b_pre, W_post, W_mix);
    split_h_kernel<<<(NN * 128 / 4 + 255) / 256, 256>>>(h);
    hist_kernel<<<(NE + 255) / 256, 256>>>(edst);
    scanA_kernel<<<SCAN_BLOCKS, 1024>>>();
    scanB_kernel<<<1, 32>>>();
    scanC_kernel<<<SCAN_BLOCKS, 1024>>>();
    scatter_kernel<<<(NE + 255) / 256, 256>>>(esrc, edst);

    const int GB = (NN + 127) / 128;

    // GEMM1: PQ = h @ B1 (+bias1)   N=256, K=128, split-A
    tgemm_kernel<<<GB * 2, 256, G2_SMEM_BYTES>>>(
        hH, hL, B1T, PQ, nullptr, NN, 256, 128, 0, 1, 2,
        bias1, nullptr, nullptr, nullptr, nullptr, nullptr, nullptr);

    aggregate_kernel<<<NN, 128>>>();

    // GEMM2: G = agg @ Wcat   N=384, K=512, single-A fp16, fp16 out
    tgemm_kernel<<<GB * 3, 256, G2_SMEM_BYTES>>>(
        agg, nullptr, WcatT, nullptr, G, NN, 384, 512, 0, 0, 3,
        nullptr, nullptr, nullptr, nullptr, nullptr, nullptr, nullptr);

    // GEMM3: hp = relu(h @ Wp0 + comb(G,s1,s2) + b_post) -> split fp16
    tgemm_kernel<<<GB, 256, G2_SMEM_BYTES>>>(
        hH, hL, Wp0T, nullptr, nullptr, NN, 128, 128, 1, 1, 1,
        b_post, G, s1, s2, nullptr, hpH, hpL);

    // GEMM4: out = h + leaky_relu(hp @ W_mix + b_mix)
    tgemm_kernel<<<GB, 256, G2_SMEM_BYTES>>>(
        hpH, hpL, WmixT, out, nullptr, NN, 128, 128, 2, 1, 1,
        b_mix, nullptr, nullptr, nullptr, h, nullptr, nullptr);
}

// round 10
// speedup vs baseline: 2.0774x; 1.5983x over previous
#include <cuda_runtime.h>
#include <cuda_fp16.h>
#include <math.h>
#include <stdint.h>

#define NN 50000
#define NE 600000
#define EPS_V 1e-5f
#define AVG_D_LOG 1.6094379124341003f

typedef unsigned long long u64;

// ---------------- scratch ----------------
__device__ __half g_P[(size_t)NN * 128];            // pre-linear src-part, fp16
__device__ float  g_Q[(size_t)NN * 128];            // pre-linear dst-part + b_pre, fp32
__device__ __half g_h16[(size_t)NN * 128];          // h as fp16 (GEMM1/3 A)
__device__ __half g_agg[(size_t)NN * 512];          // [mean|max|min|std] fp16
__device__ __half g_hp[(size_t)NN * 128];           // post-linear hidden, fp16
__device__ __half g_G[(size_t)NN * 384];            // agg @ Wcat, fp16
__device__ float g_s1[NN];
__device__ float g_s2[NN];
__device__ int   g_count[NN];
__device__ int   g_offsets[NN + 1];
__device__ int   g_cursor[NN];
__device__ int   g_sorted_src[NE];
__device__ float g_bias1[256];
__device__ __half g_B1T[256 * 128];
__device__ __half g_Wp0T[128 * 128];
__device__ __half g_WmixT[128 * 128];
__device__ __half g_WcatT[384 * 512];
__device__ int   g_blocksums[64];
__device__ int   g_blockoff[64];
__device__ int   g_is64;

// ---------------- helpers ----------------
__global__ void detect_kernel(const void* edst) {
    const int* v = (const int*)edst;
    g_is64 = (v[1] == 0 && v[3] == 0) ? 1 : 0;
}
__device__ __forceinline__ int edge_index(const void* p, int i) {
    if (g_is64) return (int)(((const long long*)p)[i]);
    return ((const int*)p)[i];
}

// ---------------- prep ----------------
__global__ void prep_kernel(const float* __restrict__ W_pre,
                            const float* __restrict__ b_pre,
                            const float* __restrict__ W_post,
                            const float* __restrict__ W_mix) {
    int idx = blockIdx.x * blockDim.x + threadIdx.x;
    if (idx < NN) g_count[idx] = 0;
    if (idx < 256) g_bias1[idx] = (idx < 128) ? 0.f : b_pre[idx - 128];
    if (idx < 256 * 128) {
        int n = idx >> 7, k = idx & 127;
        float v = (n < 128) ? W_pre[k * 128 + n] : W_pre[(128 + k) * 128 + (n - 128)];
        g_B1T[idx] = __float2half_rn(v);
    }
    if (idx < 128 * 128) {
        int n = idx >> 7, k = idx & 127;
        g_Wp0T[idx]  = __float2half_rn(W_post[k * 128 + n]);
        g_WmixT[idx] = __float2half_rn(W_mix[k * 128 + n]);
    }
    if (idx < 384 * 512) {
        int n = idx >> 9, k = idx & 511;
        int grp = n >> 7, jj = n & 127;
        g_WcatT[idx] = __float2half_rn(W_post[(size_t)(128 + grp * 512 + k) * 128 + jj]);
    }
}

__global__ void __launch_bounds__(256) conv_h_kernel(const float* __restrict__ h) {
    int i = blockIdx.x * blockDim.x + threadIdx.x;
    int idx = i * 4;
    if (idx < NN * 128) {
        float4 v = *(const float4*)(h + idx);
        __half2* dst = (__half2*)&g_h16[idx];
        dst[0] = __floats2half2_rn(v.x, v.y);
        dst[1] = __floats2half2_rn(v.z, v.w);
    }
}

// ---------------- histogram / scan / scatter ----------------
__global__ void hist_kernel(const void* __restrict__ edst) {
    int e = blockIdx.x * blockDim.x + threadIdx.x;
    if (e < NE) atomicAdd(&g_count[edge_index(edst, e)], 1);
}

#define SCAN_BLOCKS ((NN + 1023) / 1024)

__global__ void __launch_bounds__(1024) scanA_kernel() {
    __shared__ int sdata[1024];
    int tid = threadIdx.x;
    int i = blockIdx.x * 1024 + tid;
    int v = (i < NN) ? g_count[i] : 0;
    sdata[tid] = v;
    __syncthreads();
    #pragma unroll
    for (int off = 1; off < 1024; off <<= 1) {
        int t = (tid >= off) ? sdata[tid - off] : 0;
        __syncthreads();
        sdata[tid] += t;
        __syncthreads();
    }
    if (i < NN) g_offsets[i] = sdata[tid] - v;
    if (tid == 1023) g_blocksums[blockIdx.x] = sdata[1023];
}
__global__ void scanB_kernel() {
    if (threadIdx.x == 0) {
        int run = 0;
        for (int b = 0; b < SCAN_BLOCKS; b++) { g_blockoff[b] = run; run += g_blocksums[b]; }
    }
}
__global__ void __launch_bounds__(1024) scanC_kernel() {
    int i = blockIdx.x * 1024 + threadIdx.x;
    if (i < NN) {
        int o = g_offsets[i] + g_blockoff[blockIdx.x];
        g_offsets[i] = o;
        g_cursor[i] = o;
    }
    if (i == 0) g_offsets[NN] = NE;
}

__global__ void scatter_kernel(const void* __restrict__ esrc, const void* __restrict__ edst) {
    int e = blockIdx.x * blockDim.x + threadIdx.x;
    if (e < NE) {
        int d = edge_index(edst, e);
        int s = edge_index(esrc, e);
        g_sorted_src[atomicAdd(&g_cursor[d], 1)] = s;
    }
}

// ---------------- aggregate: 2 nodes per 128-thread block, half2 gather ----------------
__global__ void __launch_bounds__(128) aggregate_kernel() {
    int node = blockIdx.x * 2 + (threadIdx.x >> 6);
    int d2 = threadIdx.x & 63;
    int start = g_offsets[node];
    int end = g_offsets[node + 1];
    float2 q = *(const float2*)&g_Q[(size_t)node * 128 + 2 * d2];
    const __half2* P2 = (const __half2*)g_P;

    float sx0 = 0.f, sy0 = 0.f, qx0 = 0.f, qy0 = 0.f;
    float sx1 = 0.f, sy1 = 0.f, qx1 = 0.f, qy1 = 0.f;
    float mxx = -3.4e38f, mxy = -3.4e38f, mnx = 3.4e38f, mny = 3.4e38f;

    int i = start;
    for (; i + 1 < end; i += 2) {
        int sa = g_sorted_src[i];
        int sb = g_sorted_src[i + 1];
        float2 pa = __half22float2(P2[(size_t)sa * 64 + d2]);
        float2 pb = __half22float2(P2[(size_t)sb * 64 + d2]);
        float vax = fmaxf(pa.x + q.x, 0.f), vay = fmaxf(pa.y + q.y, 0.f);
        float vbx = fmaxf(pb.x + q.x, 0.f), vby = fmaxf(pb.y + q.y, 0.f);
        sx0 += vax; sy0 += vay; qx0 += vax * vax; qy0 += vay * vay;
        sx1 += vbx; sy1 += vby; qx1 += vbx * vbx; qy1 += vby * vby;
        mxx = fmaxf(mxx, fmaxf(vax, vbx)); mxy = fmaxf(mxy, fmaxf(vay, vby));
        mnx = fminf(mnx, fminf(vax, vbx)); mny = fminf(mny, fminf(vay, vby));
    }
    if (i < end) {
        int sa = g_sorted_src[i];
        float2 pa = __half22float2(P2[(size_t)sa * 64 + d2]);
        float vax = fmaxf(pa.x + q.x, 0.f), vay = fmaxf(pa.y + q.y, 0.f);
        sx0 += vax; sy0 += vay; qx0 += vax * vax; qy0 += vay * vay;
        mxx = fmaxf(mxx, vax); mxy = fmaxf(mxy, vay);
        mnx = fminf(mnx, vax); mny = fminf(mny, vay);
    }
    float sx = sx0 + sx1, sy = sy0 + sy1;
    float sqx = qx0 + qx1, sqy = qy0 + qy1;

    float degf = (float)(end - start);
    float inv = 1.f / degf;
    float meanx = sx * inv, meany = sy * inv;
    float varx = fmaxf(sqx * inv - meanx * meanx, 0.f);
    float vary = fmaxf(sqy * inv - meany * meany, 0.f);
    float sdx = sqrtf(varx + EPS_V), sdy = sqrtf(vary + EPS_V);

    __half2* A2 = (__half2*)&g_agg[(size_t)node * 512];
    A2[d2]            = __floats2half2_rn(meanx, meany);
    A2[64 + d2]       = __floats2half2_rn(mxx, mxy);
    A2[128 + d2]      = __floats2half2_rn(mnx, mny);
    A2[192 + d2]      = __floats2half2_rn(sdx, sdy);
    if (d2 == 0) {
        float ld = logf(degf + 1.f);
        g_s1[node] = ld / AVG_D_LOG;
        g_s2[node] = AVG_D_LOG / ld;
    }
}

// ---------------- fp16 mma.sync GEMM ----------------
// 1-D grid: bid -> (row tile = bid/nY, col tile = bid%nY) for L2 A-sharing.
// mode 0: C fp32 or Ch fp16 (+bias)
// mode 1: relu(acc + bias + G0 + s1*G1 + s2*G2) -> Ch fp16        (N=128)
// mode 2: C = resid + leaky_relu(acc + bias) fp32                 (N=128)
// mode 3: col<128 -> Ch fp16 ; col>=128 -> C fp32, both +bias     (N=256)

#define MMA16816(c, a, b) \
    asm volatile("mma.sync.aligned.m16n8k16.row.col.f32.f16.f16.f32 " \
        "{%0,%1,%2,%3}, {%4,%5,%6,%7}, {%8,%9}, {%0,%1,%2,%3};" \
        : "+f"((c)[0]), "+f"((c)[1]), "+f"((c)[2]), "+f"((c)[3]) \
        : "r"((a)[0]), "r"((a)[1]), "r"((a)[2]), "r"((a)[3]), \
          "r"((b)[0]), "r"((b)[1]))

#define LDSM4(r, a) \
    asm volatile("ldmatrix.sync.aligned.m8n8.x4.shared.b16 {%0,%1,%2,%3}, [%4];" \
        : "=r"((r)[0]), "=r"((r)[1]), "=r"((r)[2]), "=r"((r)[3]) : "r"(a))

#define CPA16(dst, src) asm volatile("cp.async.ca.shared.global [%0], [%1], 16;" :: "r"(dst), "l"(src))
#define CPA_COMMIT()    asm volatile("cp.async.commit_group;" ::: "memory")
#define CPA_WAIT0()     asm volatile("cp.async.wait_group 0;" ::: "memory")

#define G2_S 72
#define ARR_BYTES (128 * G2_S * 2)
#define STAGE_BYTES (2 * ARR_BYTES)                 // A, B
#define G2_SMEM_BYTES (2 * STAGE_BYTES)             // 73728

__global__ void __launch_bounds__(256) tgemm_kernel(
    const __half* __restrict__ ap, const __half* __restrict__ bp,
    float* __restrict__ C, __half* __restrict__ Ch,
    int M, int N, int K, int mode, int nY,
    const float* __restrict__ bias, const __half* __restrict__ Gx,
    const float* __restrict__ s1p, const float* __restrict__ s2p,
    const float* __restrict__ resid)
{
    extern __shared__ __half sm[];
    uint32_t smem_base = (uint32_t)__cvta_generic_to_shared(sm);

    int tid = threadIdx.x, lane = tid & 31, wid = tid >> 5;
    int warp_m = wid >> 2;
    int warp_n = wid & 3;
    int bid = blockIdx.x;
    int blockRow = (bid / nY) * 128, blockCol = (bid % nY) * 128;

    float acc[4][4][4];
    #pragma unroll
    for (int i = 0; i < 4; i++)
        #pragma unroll
        for (int j = 0; j < 4; j++)
            #pragma unroll
            for (int q = 0; q < 4; q++) acc[i][j][q] = 0.f;

    int ldRow = tid >> 1, ldHalf = tid & 1;
    int aRow = blockRow + ldRow; if (aRow > M - 1) aRow = M - 1;
    const __half* gA = ap + (size_t)aRow * K + ldHalf * 32;
    const __half* gB = bp + (size_t)(blockCol + ldRow) * K + ldHalf * 32;
    uint32_t sRowOff = (uint32_t)(ldRow * G2_S + ldHalf * 32) * 2;

    int lane7 = lane & 7;
    int aRowSel = ((lane >> 3) & 1) * 8;
    int aKSel   = ((lane >> 4) & 1) * 8;
    int bRowSel = ((lane >> 4) & 1) * 8;
    int bKSel   = ((lane >> 3) & 1) * 8;

    int nch = K >> 6;

    {
        uint32_t st0 = smem_base + sRowOff;
        #pragma unroll
        for (int j = 0; j < 4; j++) {
            CPA16(st0 + j * 16, (const char*)(gA + j * 8));
            CPA16(st0 + ARR_BYTES + j * 16, (const char*)(gB + j * 8));
        }
        CPA_COMMIT();
    }

    for (int ch = 0; ch < nch; ch++) {
        CPA_WAIT0();
        __syncthreads();
        if (ch + 1 < nch) {
            uint32_t stN = smem_base + ((ch + 1) & 1) * STAGE_BYTES + sRowOff;
            const __half* pA = gA + (ch + 1) * 64;
            const __half* pB = gB + (ch + 1) * 64;
            #pragma unroll
            for (int j = 0; j < 4; j++) {
                CPA16(stN + j * 16, (const char*)(pA + j * 8));
                CPA16(stN + ARR_BYTES + j * 16, (const char*)(pB + j * 8));
            }
        }
        CPA_COMMIT();

        uint32_t stC = smem_base + (ch & 1) * STAGE_BYTES;
        uint32_t bA = stC;
        uint32_t bB = stC + ARR_BYTES;

        #pragma unroll
        for (int ks = 0; ks < 4; ks++) {
            int k0 = ks * 16;
            uint32_t bh[4][2];
            #pragma unroll
            for (int p = 0; p < 2; p++) {
                uint32_t off = (uint32_t)((warp_n * 32 + p * 16 + bRowSel + lane7) * G2_S + k0 + bKSel) * 2;
                LDSM4(&bh[2 * p][0], bB + off);
            }
            #pragma unroll
            for (int mt = 0; mt < 4; mt++) {
                uint32_t off = (uint32_t)((warp_m * 64 + mt * 16 + aRowSel + lane7) * G2_S + k0 + aKSel) * 2;
                uint32_t ah[4];
                LDSM4(ah, bA + off);
                #pragma unroll
                for (int nt = 0; nt < 4; nt++)
                    MMA16816(acc[mt][nt], ah, bh[nt]);
            }
        }
    }

    // epilogue
    int fr = lane >> 2;
    #pragma unroll
    for (int mt = 0; mt < 4; mt++) {
        int row0 = blockRow + warp_m * 64 + mt * 16 + fr;
        #pragma unroll
        for (int half = 0; half < 2; half++) {
            int row = row0 + half * 8;
            if (row >= M) continue;
            #pragma unroll
            for (int nt = 0; nt < 4; nt++) {
                int col = blockCol + warp_n * 32 + nt * 8 + ((lane & 3) * 2);
                float v0 = acc[mt][nt][half * 2];
                float v1 = acc[mt][nt][half * 2 + 1];
                if (bias) { v0 += bias[col]; v1 += bias[col + 1]; }
                if (mode == 0) {
                    if (Ch) *(__half2*)&Ch[(size_t)row * N + col] = __floats2half2_rn(v0, v1);
                    else    *(float2*)&C[(size_t)row * N + col] = make_float2(v0, v1);
                } else if (mode == 1) {
                    float s1v = s1p[row], s2v = s2p[row];
                    const __half* g = &Gx[(size_t)row * 384];
                    float2 g0 = __half22float2(*(const __half2*)&g[col]);
                    float2 g1 = __half22float2(*(const __half2*)&g[col + 128]);
                    float2 g2 = __half22float2(*(const __half2*)&g[col + 256]);
                    v0 += g0.x + s1v * g1.x + s2v * g2.x;
                    v1 += g0.y + s1v * g1.y + s2v * g2.y;
                    v0 = fmaxf(v0, 0.f);
                    v1 = fmaxf(v1, 0.f);
                    *(__half2*)&Ch[(size_t)row * 128 + col] = __floats2half2_rn(v0, v1);
                } else if (mode == 2) {
                    v0 = (v0 > 0.f) ? v0 : 0.01f * v0;
                    v1 = (v1 > 0.f) ? v1 : 0.01f * v1;
                    size_t o = (size_t)row * 128 + col;
                    v0 += resid[o];
                    v1 += resid[o + 1];
                    *(float2*)&C[o] = make_float2(v0, v1);
                } else {
                    // mode 3: PQ split output
                    if (col < 128) {
                        *(__half2*)&Ch[(size_t)row * 128 + col] = __floats2half2_rn(v0, v1);
                    } else {
                        *(float2*)&C[(size_t)row * 128 + (col - 128)] = make_float2(v0, v1);
                    }
                }
            }
        }
    }
}

// ---------------- launch ----------------
extern "C" void kernel_launch(void* const* d_in, const int* in_sizes, int n_in,
                              void* d_out, int out_size) {
    const float* h      = (const float*)d_in[0];
    const void*  esrc   = d_in[1];
    const void*  edst   = d_in[2];
    const float* W_pre  = (const float*)d_in[3];
    const float* b_pre  = (const float*)d_in[4];
    const float* W_post = (const float*)d_in[5];
    const float* b_post = (const float*)d_in[6];
    const float* W_mix  = (const float*)d_in[7];
    const float* b_mix  = (const float*)d_in[8];
    float* out = (float*)d_out;

    float *Q, *s1, *s2, *bias1;
    __half *P, *h16, *agg, *hp, *G;
    __half *B1T, *Wp0T, *WmixT, *WcatT;
    cudaGetSymbolAddress((void**)&P, g_P);
    cudaGetSymbolAddress((void**)&Q, g_Q);
    cudaGetSymbolAddress((void**)&h16, g_h16);
    cudaGetSymbolAddress((void**)&agg, g_agg);
    cudaGetSymbolAddress((void**)&hp, g_hp);
    cudaGetSymbolAddress((void**)&G, g_G);
    cudaGetSymbolAddress((void**)&s1, g_s1);
    cudaGetSymbolAddress((void**)&s2, g_s2);
    cudaGetSymbolAddress((void**)&bias1, g_bias1);
    cudaGetSymbolAddress((void**)&B1T, g_B1T);
    cudaGetSymbolAddress((void**)&Wp0T, g_Wp0T);
    cudaGetSymbolAddress((void**)&WmixT, g_WmixT);
    cudaGetSymbolAddress((void**)&WcatT, g_WcatT);

    static int smem_set = 0;
    if (!smem_set) {
        cudaFuncSetAttribute(tgemm_kernel, cudaFuncAttributeMaxDynamicSharedMemorySize, G2_SMEM_BYTES);
        smem_set = 1;
    }

    detect_kernel<<<1, 1>>>(edst);
    prep_kernel<<<768, 256>>>(W_pre, b_pre, W_post, W_mix);
    conv_h_kernel<<<(NN * 128 / 4 + 255) / 256, 256>>>(h);
    hist_kernel<<<(NE + 255) / 256, 256>>>(edst);
    scanA_kernel<<<SCAN_BLOCKS, 1024>>>();
    scanB_kernel<<<1, 32>>>();
    scanC_kernel<<<SCAN_BLOCKS, 1024>>>();
    scatter_kernel<<<(NE + 255) / 256, 256>>>(esrc, edst);

    const int GB = (NN + 127) / 128;

    // GEMM1 (mode 3): [P fp16 | Q fp32] = h16 @ B1 + bias1   N=256, K=128
    tgemm_kernel<<<GB * 2, 256, G2_SMEM_BYTES>>>(
        h16, B1T, Q, P, NN, 256, 128, 3, 2,
        bias1, nullptr, nullptr, nullptr, nullptr);

    aggregate_kernel<<<NN / 2, 128>>>();

    // GEMM2 (mode 0): G fp16 = agg @ Wcat   N=384, K=512
    tgemm_kernel<<<GB * 3, 256, G2_SMEM_BYTES>>>(
        agg, WcatT, nullptr, G, NN, 384, 512, 0, 3,
        nullptr, nullptr, nullptr, nullptr, nullptr);

    // GEMM3 (mode 1): hp fp16 = relu(h16 @ Wp0 + comb(G,s1,s2) + b_post)
    tgemm_kernel<<<GB, 256, G2_SMEM_BYTES>>>(
        h16, Wp0T, nullptr, hp, NN, 128, 128, 1, 1,
        b_post, G, s1, s2, nullptr);

    // GEMM4 (mode 2): out = h + leaky_relu(hp @ W_mix + b_mix)
    tgemm_kernel<<<GB, 256, G2_SMEM_BYTES>>>(
        hp, WmixT, out, nullptr, NN, 128, 128, 2, 1,
        b_mix, nullptr, nullptr, nullptr, h);
}

// round 12
// speedup vs baseline: 2.1302x; 1.0254x over previous
#include <cuda_runtime.h>
#include <cuda_fp16.h>
#include <math.h>
#include <stdint.h>

#define NN 50000
#define NE 600000
#define EPS_V 1e-5f
#define AVG_D_LOG 1.6094379124341003f

typedef unsigned long long u64;

// ---------------- scratch ----------------
__device__ __half g_P[(size_t)NN * 128];            // pre-linear src-part, fp16
__device__ float  g_Q[(size_t)NN * 128];            // pre-linear dst-part + b_pre, fp32
__device__ __half g_h16[(size_t)NN * 128];          // h as fp16
__device__ __half g_agg[(size_t)NN * 512];          // [mean|max|min|std] fp16
__device__ __half g_hp[(size_t)NN * 128];           // post-linear hidden, fp16
__device__ __half g_G[(size_t)NN * 384];            // agg @ Wcat, fp16
__device__ float g_s1[NN];
__device__ float g_s2[NN];
__device__ int   g_count[NN];
__device__ int   g_offsets[NN + 1];
__device__ int   g_cursor[NN];
__device__ int   g_sorted_src[NE];
__device__ float g_bias1[256];
__device__ __half g_B1T[256 * 128];
__device__ __half g_Wp0T[128 * 128];
__device__ __half g_WmixT[128 * 128];
__device__ __half g_WcatT[384 * 512];
__device__ int   g_blocksums[64];
__device__ int   g_blockoff[64];
__device__ int   g_is64;

// ---------------- helpers ----------------
__global__ void detect_kernel(const void* edst) {
    const int* v = (const int*)edst;
    g_is64 = (v[1] == 0 && v[3] == 0) ? 1 : 0;
}
__device__ __forceinline__ int edge_index(const void* p, int i) {
    if (g_is64) return (int)(((const long long*)p)[i]);
    return ((const int*)p)[i];
}

// ---------------- prep (weights only — NO g_count here; sort chain owns it) ----------------
__global__ void prep_kernel(const float* __restrict__ W_pre,
                            const float* __restrict__ b_pre,
                            const float* __restrict__ W_post,
                            const float* __restrict__ W_mix) {
    int idx = blockIdx.x * blockDim.x + threadIdx.x;
    if (idx < 256) g_bias1[idx] = (idx < 128) ? 0.f : b_pre[idx - 128];
    if (idx < 256 * 128) {
        int n = idx >> 7, k = idx & 127;
        float v = (n < 128) ? W_pre[k * 128 + n] : W_pre[(128 + k) * 128 + (n - 128)];
        g_B1T[idx] = __float2half_rn(v);
    }
    if (idx < 128 * 128) {
        int n = idx >> 7, k = idx & 127;
        g_Wp0T[idx]  = __float2half_rn(W_post[k * 128 + n]);
        g_WmixT[idx] = __float2half_rn(W_mix[k * 128 + n]);
    }
    if (idx < 384 * 512) {
        int n = idx >> 9, k = idx & 511;
        int grp = n >> 7, jj = n & 127;
        g_WcatT[idx] = __float2half_rn(W_post[(size_t)(128 + grp * 512 + k) * 128 + jj]);
    }
}

__global__ void __launch_bounds__(256) conv_h_kernel(const float* __restrict__ h) {
    int i = blockIdx.x * blockDim.x + threadIdx.x;
    int idx = i * 4;
    if (idx < NN * 128) {
        float4 v = *(const float4*)(h + idx);
        __half2* dst = (__half2*)&g_h16[idx];
        dst[0] = __floats2half2_rn(v.x, v.y);
        dst[1] = __floats2half2_rn(v.z, v.w);
    }
}

// ---------------- sort chain: zero / histogram / scan / scatter ----------------
__global__ void __launch_bounds__(256) zero_count_kernel() {
    int i = blockIdx.x * blockDim.x + threadIdx.x;
    if (i < NN) g_count[i] = 0;
}

__global__ void hist_kernel(const void* __restrict__ edst) {
    int e = blockIdx.x * blockDim.x + threadIdx.x;
    if (e < NE) atomicAdd(&g_count[edge_index(edst, e)], 1);
}

#define SCAN_BLOCKS ((NN + 1023) / 1024)

__global__ void __launch_bounds__(1024) scanA_kernel() {
    __shared__ int sdata[1024];
    int tid = threadIdx.x;
    int i = blockIdx.x * 1024 + tid;
    int v = (i < NN) ? g_count[i] : 0;
    sdata[tid] = v;
    __syncthreads();
    #pragma unroll
    for (int off = 1; off < 1024; off <<= 1) {
        int t = (tid >= off) ? sdata[tid - off] : 0;
        __syncthreads();
        sdata[tid] += t;
        __syncthreads();
    }
    if (i < NN) g_offsets[i] = sdata[tid] - v;
    if (tid == 1023) g_blocksums[blockIdx.x] = sdata[1023];
}
__global__ void scanB_kernel() {
    if (threadIdx.x == 0) {
        int run = 0;
        for (int b = 0; b < SCAN_BLOCKS; b++) { g_blockoff[b] = run; run += g_blocksums[b]; }
    }
}
__global__ void __launch_bounds__(1024) scanC_kernel() {
    int i = blockIdx.x * 1024 + threadIdx.x;
    if (i < NN) {
        int o = g_offsets[i] + g_blockoff[blockIdx.x];
        g_offsets[i] = o;
        g_cursor[i] = o;
    }
    if (i == 0) g_offsets[NN] = NE;
}

__global__ void scatter_kernel(const void* __restrict__ esrc, const void* __restrict__ edst) {
    int e = blockIdx.x * blockDim.x + threadIdx.x;
    if (e < NE) {
        int d = edge_index(edst, e);
        int s = edge_index(esrc, e);
        g_sorted_src[atomicAdd(&g_cursor[d], 1)] = s;
    }
}

// ---------------- aggregate: 2 nodes/block, half2 gather, unroll-4 ----------------
__global__ void __launch_bounds__(128) aggregate_kernel() {
    int node = blockIdx.x * 2 + (threadIdx.x >> 6);
    int d2 = threadIdx.x & 63;
    int start = g_offsets[node];
    int end = g_offsets[node + 1];
    float2 q = *(const float2*)&g_Q[(size_t)node * 128 + 2 * d2];
    const __half2* P2 = (const __half2*)g_P;

    float sx[4] = {0.f, 0.f, 0.f, 0.f}, sy[4] = {0.f, 0.f, 0.f, 0.f};
    float qx[4] = {0.f, 0.f, 0.f, 0.f}, qy[4] = {0.f, 0.f, 0.f, 0.f};
    float mxx = -3.4e38f, mxy = -3.4e38f, mnx = 3.4e38f, mny = 3.4e38f;

    int i = start;
    for (; i + 3 < end; i += 4) {
        int srcs[4];
        #pragma unroll
        for (int u = 0; u < 4; u++) srcs[u] = g_sorted_src[i + u];
        float2 p[4];
        #pragma unroll
        for (int u = 0; u < 4; u++) p[u] = __half22float2(P2[(size_t)srcs[u] * 64 + d2]);
        #pragma unroll
        for (int u = 0; u < 4; u++) {
            float vx = fmaxf(p[u].x + q.x, 0.f), vy = fmaxf(p[u].y + q.y, 0.f);
            sx[u] += vx; sy[u] += vy; qx[u] += vx * vx; qy[u] += vy * vy;
            mxx = fmaxf(mxx, vx); mxy = fmaxf(mxy, vy);
            mnx = fminf(mnx, vx); mny = fminf(mny, vy);
        }
    }
    for (; i < end; i++) {
        int s_ = g_sorted_src[i];
        float2 p = __half22float2(P2[(size_t)s_ * 64 + d2]);
        float vx = fmaxf(p.x + q.x, 0.f), vy = fmaxf(p.y + q.y, 0.f);
        sx[0] += vx; sy[0] += vy; qx[0] += vx * vx; qy[0] += vy * vy;
        mxx = fmaxf(mxx, vx); mxy = fmaxf(mxy, vy);
        mnx = fminf(mnx, vx); mny = fminf(mny, vy);
    }
    float sxx = (sx[0] + sx[1]) + (sx[2] + sx[3]);
    float syy = (sy[0] + sy[1]) + (sy[2] + sy[3]);
    float sqx = (qx[0] + qx[1]) + (qx[2] + qx[3]);
    float sqy = (qy[0] + qy[1]) + (qy[2] + qy[3]);

    float degf = (float)(end - start);
    float inv = 1.f / degf;
    float meanx = sxx * inv, meany = syy * inv;
    float varx = fmaxf(sqx * inv - meanx * meanx, 0.f);
    float vary = fmaxf(sqy * inv - meany * meany, 0.f);
    float sdx = sqrtf(varx + EPS_V), sdy = sqrtf(vary + EPS_V);

    __half2* A2 = (__half2*)&g_agg[(size_t)node * 512];
    A2[d2]       = __floats2half2_rn(meanx, meany);
    A2[64 + d2]  = __floats2half2_rn(mxx, mxy);
    A2[128 + d2] = __floats2half2_rn(mnx, mny);
    A2[192 + d2] = __floats2half2_rn(sdx, sdy);
    if (d2 == 0) {
        float ld = logf(degf + 1.f);
        g_s1[node] = ld / AVG_D_LOG;
        g_s2[node] = AVG_D_LOG / ld;
    }
}

// ---------------- fp16 mma.sync GEMM ----------------
// 1-D grid: bid -> (row tile = bid/nY, col tile = bid%nY) for L2 A-sharing.
// mode 0: C fp32 or Ch fp16 (+bias)
// mode 1: relu(acc + bias + G0 + s1*G1 + s2*G2) -> Ch fp16        (N=128)
// mode 2: C = resid + leaky_relu(acc + bias) fp32                 (N=128)
// mode 3: col<128 -> Ch fp16 ; col>=128 -> C fp32, both +bias     (N=256)

#define MMA16816(c, a, b) \
    asm volatile("mma.sync.aligned.m16n8k16.row.col.f32.f16.f16.f32 " \
        "{%0,%1,%2,%3}, {%4,%5,%6,%7}, {%8,%9}, {%0,%1,%2,%3};" \
        : "+f"((c)[0]), "+f"((c)[1]), "+f"((c)[2]), "+f"((c)[3]) \
        : "r"((a)[0]), "r"((a)[1]), "r"((a)[2]), "r"((a)[3]), \
          "r"((b)[0]), "r"((b)[1]))

#define LDSM4(r, a) \
    asm volatile("ldmatrix.sync.aligned.m8n8.x4.shared.b16 {%0,%1,%2,%3}, [%4];" \
        : "=r"((r)[0]), "=r"((r)[1]), "=r"((r)[2]), "=r"((r)[3]) : "r"(a))

#define CPA16(dst, src) asm volatile("cp.async.ca.shared.global [%0], [%1], 16;" :: "r"(dst), "l"(src))
#define CPA_COMMIT()    asm volatile("cp.async.commit_group;" ::: "memory")
#define CPA_WAIT0()     asm volatile("cp.async.wait_group 0;" ::: "memory")

#define G2_S 72
#define ARR_BYTES (128 * G2_S * 2)
#define STAGE_BYTES (2 * ARR_BYTES)
#define G2_SMEM_BYTES (2 * STAGE_BYTES)             // 73728

__global__ void __launch_bounds__(256) tgemm_kernel(
    const __half* __restrict__ ap, const __half* __restrict__ bp,
    float* __restrict__ C, __half* __restrict__ Ch,
    int M, int N, int K, int mode, int nY,
    const float* __restrict__ bias, const __half* __restrict__ Gx,
    const float* __restrict__ s1p, const float* __restrict__ s2p,
    const float* __restrict__ resid)
{
    extern __shared__ __half sm[];
    uint32_t smem_base = (uint32_t)__cvta_generic_to_shared(sm);

    int tid = threadIdx.x, lane = tid & 31, wid = tid >> 5;
    int warp_m = wid >> 2;
    int warp_n = wid & 3;
    int bid = blockIdx.x;
    int blockRow = (bid / nY) * 128, blockCol = (bid % nY) * 128;

    float acc[4][4][4];
    #pragma unroll
    for (int i = 0; i < 4; i++)
        #pragma unroll
        for (int j = 0; j < 4; j++)
            #pragma unroll
            for (int q = 0; q < 4; q++) acc[i][j][q] = 0.f;

    int ldRow = tid >> 1, ldHalf = tid & 1;
    int aRow = blockRow + ldRow; if (aRow > M - 1) aRow = M - 1;
    const __half* gA = ap + (size_t)aRow * K + ldHalf * 32;
    const __half* gB = bp + (size_t)(blockCol + ldRow) * K + ldHalf * 32;
    uint32_t sRowOff = (uint32_t)(ldRow * G2_S + ldHalf * 32) * 2;

    int lane7 = lane & 7;
    int aRowSel = ((lane >> 3) & 1) * 8;
    int aKSel   = ((lane >> 4) & 1) * 8;
    int bRowSel = ((lane >> 4) & 1) * 8;
    int bKSel   = ((lane >> 3) & 1) * 8;

    int nch = K >> 6;

    {
        uint32_t st0 = smem_base + sRowOff;
        #pragma unroll
        for (int j = 0; j < 4; j++) {
            CPA16(st0 + j * 16, (const char*)(gA + j * 8));
            CPA16(st0 + ARR_BYTES + j * 16, (const char*)(gB + j * 8));
        }
        CPA_COMMIT();
    }

    for (int ch = 0; ch < nch; ch++) {
        CPA_WAIT0();
        __syncthreads();
        if (ch + 1 < nch) {
            uint32_t stN = smem_base + ((ch + 1) & 1) * STAGE_BYTES + sRowOff;
            const __half* pA = gA + (ch + 1) * 64;
            const __half* pB = gB + (ch + 1) * 64;
            #pragma unroll
            for (int j = 0; j < 4; j++) {
                CPA16(stN + j * 16, (const char*)(pA + j * 8));
                CPA16(stN + ARR_BYTES + j * 16, (const char*)(pB + j * 8));
            }
        }
        CPA_COMMIT();

        uint32_t stC = smem_base + (ch & 1) * STAGE_BYTES;
        uint32_t bA = stC;
        uint32_t bB = stC + ARR_BYTES;

        #pragma unroll
        for (int ks = 0; ks < 4; ks++) {
            int k0 = ks * 16;
            uint32_t bh[4][2];
            #pragma unroll
            for (int p = 0; p < 2; p++) {
                uint32_t off = (uint32_t)((warp_n * 32 + p * 16 + bRowSel + lane7) * G2_S + k0 + bKSel) * 2;
                LDSM4(&bh[2 * p][0], bB + off);
            }
            #pragma unroll
            for (int mt = 0; mt < 4; mt++) {
                uint32_t off = (uint32_t)((warp_m * 64 + mt * 16 + aRowSel + lane7) * G2_S + k0 + aKSel) * 2;
                uint32_t ah[4];
                LDSM4(ah, bA + off);
                #pragma unroll
                for (int nt = 0; nt < 4; nt++)
                    MMA16816(acc[mt][nt], ah, bh[nt]);
            }
        }
    }

    // epilogue
    int fr = lane >> 2;
    #pragma unroll
    for (int mt = 0; mt < 4; mt++) {
        int row0 = blockRow + warp_m * 64 + mt * 16 + fr;
        #pragma unroll
        for (int half = 0; half < 2; half++) {
            int row = row0 + half * 8;
            if (row >= M) continue;
            #pragma unroll
            for (int nt = 0; nt < 4; nt++) {
                int col = blockCol + warp_n * 32 + nt * 8 + ((lane & 3) * 2);
                float v0 = acc[mt][nt][half * 2];
                float v1 = acc[mt][nt][half * 2 + 1];
                if (bias) { v0 += bias[col]; v1 += bias[col + 1]; }
                if (mode == 0) {
                    if (Ch) *(__half2*)&Ch[(size_t)row * N + col] = __floats2half2_rn(v0, v1);
                    else    *(float2*)&C[(size_t)row * N + col] = make_float2(v0, v1);
                } else if (mode == 1) {
                    float s1v = s1p[row], s2v = s2p[row];
                    const __half* g = &Gx[(size_t)row * 384];
                    float2 g0 = __half22float2(*(const __half2*)&g[col]);
                    float2 g1 = __half22float2(*(const __half2*)&g[col + 128]);
                    float2 g2 = __half22float2(*(const __half2*)&g[col + 256]);
                    v0 += g0.x + s1v * g1.x + s2v * g2.x;
                    v1 += g0.y + s1v * g1.y + s2v * g2.y;
                    v0 = fmaxf(v0, 0.f);
                    v1 = fmaxf(v1, 0.f);
                    *(__half2*)&Ch[(size_t)row * 128 + col] = __floats2half2_rn(v0, v1);
                } else if (mode == 2) {
                    v0 = (v0 > 0.f) ? v0 : 0.01f * v0;
                    v1 = (v1 > 0.f) ? v1 : 0.01f * v1;
                    size_t o = (size_t)row * 128 + col;
                    v0 += resid[o];
                    v1 += resid[o + 1];
                    *(float2*)&C[o] = make_float2(v0, v1);
                } else {
                    if (col < 128) {
                        *(__half2*)&Ch[(size_t)row * 128 + col] = __floats2half2_rn(v0, v1);
                    } else {
                        *(float2*)&C[(size_t)row * 128 + (col - 128)] = make_float2(v0, v1);
                    }
                }
            }
        }
    }
}

// ---------------- launch ----------------
extern "C" void kernel_launch(void* const* d_in, const int* in_sizes, int n_in,
                              void* d_out, int out_size) {
    const float* h      = (const float*)d_in[0];
    const void*  esrc   = d_in[1];
    const void*  edst   = d_in[2];
    const float* W_pre  = (const float*)d_in[3];
    const float* b_pre  = (const float*)d_in[4];
    const float* W_post = (const float*)d_in[5];
    const float* b_post = (const float*)d_in[6];
    const float* W_mix  = (const float*)d_in[7];
    const float* b_mix  = (const float*)d_in[8];
    float* out = (float*)d_out;

    float *Q, *s1, *s2, *bias1;
    __half *P, *h16, *agg, *hp, *G;
    __half *B1T, *Wp0T, *WmixT, *WcatT;
    cudaGetSymbolAddress((void**)&P, g_P);
    cudaGetSymbolAddress((void**)&Q, g_Q);
    cudaGetSymbolAddress((void**)&h16, g_h16);
    cudaGetSymbolAddress((void**)&agg, g_agg);
    cudaGetSymbolAddress((void**)&hp, g_hp);
    cudaGetSymbolAddress((void**)&G, g_G);
    cudaGetSymbolAddress((void**)&s1, g_s1);
    cudaGetSymbolAddress((void**)&s2, g_s2);
    cudaGetSymbolAddress((void**)&bias1, g_bias1);
    cudaGetSymbolAddress((void**)&B1T, g_B1T);
    cudaGetSymbolAddress((void**)&Wp0T, g_Wp0T);
    cudaGetSymbolAddress((void**)&WmixT, g_WmixT);
    cudaGetSymbolAddress((void**)&WcatT, g_WcatT);

    static int init_done = 0;
    static cudaStream_t s_side;
    static cudaEvent_t ev_fork, ev_join;
    if (!init_done) {
        cudaFuncSetAttribute(tgemm_kernel, cudaFuncAttributeMaxDynamicSharedMemorySize, G2_SMEM_BYTES);
        cudaStreamCreateWithFlags(&s_side, cudaStreamNonBlocking);
        cudaEventCreateWithFlags(&ev_fork, cudaEventDisableTiming);
        cudaEventCreateWithFlags(&ev_join, cudaEventDisableTiming);
        init_done = 1;
    }

    // serial prologue on main stream
    detect_kernel<<<1, 1>>>(edst);

    // fork: fully self-contained sort chain on side stream
    cudaEventRecord(ev_fork, 0);
    cudaStreamWaitEvent(s_side, ev_fork, 0);
    zero_count_kernel<<<(NN + 255) / 256, 256, 0, s_side>>>();
    hist_kernel<<<(NE + 255) / 256, 256, 0, s_side>>>(edst);
    scanA_kernel<<<SCAN_BLOCKS, 1024, 0, s_side>>>();
    scanB_kernel<<<1, 32, 0, s_side>>>();
    scanC_kernel<<<SCAN_BLOCKS, 1024, 0, s_side>>>();
    scatter_kernel<<<(NE + 255) / 256, 256, 0, s_side>>>(esrc, edst);
    cudaEventRecord(ev_join, s_side);

    // main stream: weight prep + h conversion + GEMM1 (touches none of sort state)
    prep_kernel<<<768, 256>>>(W_pre, b_pre, W_post, W_mix);
    conv_h_kernel<<<(NN * 128 / 4 + 255) / 256, 256>>>(h);

    const int GB = (NN + 127) / 128;

    // GEMM1 (mode 3): [P fp16 | Q fp32] = h16 @ B1 + bias1   N=256, K=128
    tgemm_kernel<<<GB * 2, 256, G2_SMEM_BYTES>>>(
        h16, B1T, Q, P, NN, 256, 128, 3, 2,
        bias1, nullptr, nullptr, nullptr, nullptr);

    // join: aggregate needs CSR + PQ
    cudaStreamWaitEvent(0, ev_join, 0);

    aggregate_kernel<<<NN / 2, 128>>>();

    // GEMM2 (mode 0): G fp16 = agg @ Wcat   N=384, K=512
    tgemm_kernel<<<GB * 3, 256, G2_SMEM_BYTES>>>(
        agg, WcatT, nullptr, G, NN, 384, 512, 0, 3,
        nullptr, nullptr, nullptr, nullptr, nullptr);

    // GEMM3 (mode 1): hp fp16 = relu(h16 @ Wp0 + comb(G,s1,s2) + b_post)
    tgemm_kernel<<<GB, 256, G2_SMEM_BYTES>>>(
        h16, Wp0T, nullptr, hp, NN, 128, 128, 1, 1,
        b_post, G, s1, s2, nullptr);

    // GEMM4 (mode 2): out = h + leaky_relu(hp @ W_mix + b_mix)
    tgemm_kernel<<<GB, 256, G2_SMEM_BYTES>>>(
        hp, WmixT, out, nullptr, NN, 128, 128, 2, 1,
        b_mix, nullptr, nullptr, nullptr, h);
}